// round 13
// baseline (speedup 1.0000x reference)
#include <cuda_runtime.h>
#include <cuda_fp16.h>
#include <math.h>
#include <stdint.h>

// Problem dims (fixed)
#define B_   64
#define S_   512
#define D_   256
#define ROWS (B_ * S_)          // 32768
#define WSZ  (D_ * D_)          // 65536 per-layer weight size
#define L2E  1.4426950408889634f

// ---------------------------------------------------------------------------
// Scratch (device globals; no allocation allowed)
// ---------------------------------------------------------------------------
__device__ __half g_H16[ROWS * D_];
__device__ __half g_Q16[ROWS * D_];
__device__ __half g_K16[ROWS * D_];
__device__ __half g_V16[ROWS * D_];
__device__ __half g_O16[ROWS * D_];
__device__ __half g_C16[ROWS * D_];
__device__ __half g_F16[ROWS * D_];
__device__ __half g_WT16[3 * 3 * WSZ];        // wo,w1,w2 transposed fp16
__device__ __half g_WQKV[3 * 3 * WSZ];        // per-layer [768][256] fp16
__device__ float  g_H32[ROWS * D_];           // LN(x) fp32 (residual use)

// ---------------------------------------------------------------------------
// helpers
// ---------------------------------------------------------------------------
__device__ __forceinline__ uint32_t smem_u32(const void* p) {
    uint32_t a;
    asm("{ .reg .u64 t; cvta.to.shared.u64 t, %1; cvt.u32.u64 %0, t; }"
        : "=r"(a) : "l"(p));
    return a;
}
__device__ __forceinline__ uint32_t swz(uint32_t byte) {   // SW128
    return byte ^ ((byte >> 3) & 0x70);
}
__device__ __forceinline__ void cp16(uint32_t dst, const void* src) {
    asm volatile("cp.async.cg.shared.global [%0], [%1], 16;"
                 :: "r"(dst), "l"(src) : "memory");
}
__device__ __forceinline__ void cp_commit() {
    asm volatile("cp.async.commit_group;" ::: "memory");
}
__device__ __forceinline__ void ldm4(uint32_t* r, uint32_t a) {
    asm volatile("ldmatrix.sync.aligned.m8n8.x4.shared.b16 {%0,%1,%2,%3}, [%4];"
                 : "=r"(r[0]), "=r"(r[1]), "=r"(r[2]), "=r"(r[3]) : "r"(a));
}
__device__ __forceinline__ void ldm4t(uint32_t* r, uint32_t a) {
    asm volatile("ldmatrix.sync.aligned.m8n8.x4.trans.shared.b16 {%0,%1,%2,%3}, [%4];"
                 : "=r"(r[0]), "=r"(r[1]), "=r"(r[2]), "=r"(r[3]) : "r"(a));
}
__device__ __forceinline__ void mma_f16(float* d, const uint32_t* a, const uint32_t* b) {
    asm volatile(
        "mma.sync.aligned.m16n8k16.row.col.f32.f16.f16.f32 "
        "{%0,%1,%2,%3}, {%4,%5,%6,%7}, {%8,%9}, {%0,%1,%2,%3};"
        : "+f"(d[0]), "+f"(d[1]), "+f"(d[2]), "+f"(d[3])
        : "r"(a[0]), "r"(a[1]), "r"(a[2]), "r"(a[3]), "r"(b[0]), "r"(b[1]));
}
__device__ __forceinline__ uint32_t pk32(float a, float b) {
    __half2 h = __floats2half2_rn(a, b);
    return *reinterpret_cast<uint32_t*>(&h);
}
__device__ __forceinline__ void st2(float* p, float a, float b) {
    *(float2*)p = make_float2(a, b);
}
__device__ __forceinline__ void st2(__half* p, float a, float b) {
    *(__half2*)p = __floats2half2_rn(a, b);
}

// ---------------------------------------------------------------------------
// Weight transpose: float in -> half out, out[c][r] = in[r][c]; z-stride param
// ---------------------------------------------------------------------------
__global__ void trW_k(const float* __restrict__ in, __half* __restrict__ out,
                      int rows, int cols, long ostride)
{
    __shared__ float t[32][33];
    in  += blockIdx.z * (long)rows * cols;
    out += blockIdx.z * ostride;
    const int r0 = blockIdx.y * 32, c0 = blockIdx.x * 32;
    const int tx = threadIdx.x, ty = threadIdx.y;
    #pragma unroll
    for (int i = 0; i < 32; i += 8)
        t[ty + i][tx] = in[(long)(r0 + ty + i) * cols + c0 + tx];
    __syncthreads();
    #pragma unroll
    for (int i = 0; i < 32; i += 8)
        out[(long)(c0 + ty + i) * rows + r0 + tx] = __float2half_rn(t[tx][ty + i]);
}

// ---------------------------------------------------------------------------
// LayerNorm (used once, layer 0 input): one warp per row -> H16 + H32
// ---------------------------------------------------------------------------
__global__ void ln_k(const float* __restrict__ in,
                     const float* __restrict__ g, const float* __restrict__ b,
                     __half* __restrict__ out16, float* __restrict__ out32, int rows)
{
    int warp = (blockIdx.x * blockDim.x + threadIdx.x) >> 5;
    int lane = threadIdx.x & 31;
    if (warp >= rows) return;

    const float4* x4 = (const float4*)(in + (long)warp * D_);
    float4 v0 = x4[lane];
    float4 v1 = x4[lane + 32];

    float s = v0.x + v0.y + v0.z + v0.w + v1.x + v1.y + v1.z + v1.w;
    #pragma unroll
    for (int o = 16; o; o >>= 1) s += __shfl_xor_sync(0xffffffffu, s, o);
    float mean = s * (1.0f / 256.0f);

    float d0x = v0.x - mean, d0y = v0.y - mean, d0z = v0.z - mean, d0w = v0.w - mean;
    float d1x = v1.x - mean, d1y = v1.y - mean, d1z = v1.z - mean, d1w = v1.w - mean;
    float q = d0x*d0x + d0y*d0y + d0z*d0z + d0w*d0w
            + d1x*d1x + d1y*d1y + d1z*d1z + d1w*d1w;
    #pragma unroll
    for (int o = 16; o; o >>= 1) q += __shfl_xor_sync(0xffffffffu, q, o);
    float inv = rsqrtf(q * (1.0f / 256.0f) + 1e-5f);

    const float4* g4 = (const float4*)g;
    const float4* b4 = (const float4*)b;
    float4 gv0 = g4[lane], gv1 = g4[lane + 32];
    float4 bv0 = b4[lane], bv1 = b4[lane + 32];

    float4 o0, o1;
    o0.x = d0x * inv * gv0.x + bv0.x;  o0.y = d0y * inv * gv0.y + bv0.y;
    o0.z = d0z * inv * gv0.z + bv0.z;  o0.w = d0w * inv * gv0.w + bv0.w;
    o1.x = d1x * inv * gv1.x + bv1.x;  o1.y = d1y * inv * gv1.y + bv1.y;
    o1.z = d1z * inv * gv1.z + bv1.z;  o1.w = d1w * inv * gv1.w + bv1.w;

    float4* out4 = (float4*)(out32 + (long)warp * D_);
    out4[lane]      = o0;
    out4[lane + 32] = o1;
    __half2* oh = (__half2*)(out16 + (long)warp * D_);
    oh[lane * 2]            = __floats2half2_rn(o0.x, o0.y);
    oh[lane * 2 + 1]        = __floats2half2_rn(o0.z, o0.w);
    oh[(lane + 32) * 2]     = __floats2half2_rn(o1.x, o1.y);
    oh[(lane + 32) * 2 + 1] = __floats2half2_rn(o1.z, o1.w);
}

// ---------------------------------------------------------------------------
// Fused flash attention, 100KB smem (2 CTAs/SM).
// Q is staged through the KV buffer region once (fragments then live in regs),
// then the KV double-buffer pipeline overwrites it.
// smem: btab 4KB | bufA 48KB (K 32K + V 16K) | bufB 48KB  = 100KB
// Softmax without max-subtraction (exact identity here; logits are O(1)).
// ---------------------------------------------------------------------------
__global__ void __launch_bounds__(256, 2)
flash_k(const __half* __restrict__ Qg, const __half* __restrict__ Kg,
        const __half* __restrict__ Vg, const int* __restrict__ mask,
        const float* __restrict__ btab, __half* __restrict__ Og)
{
    extern __shared__ char sm[];
    const uint32_t smu = smem_u32(sm);
    float* btab_s = (float*)sm;
    const uint32_t Qu  = smu + 4096;          // Q staging (transient, 64KB)
    const uint32_t KV0 = smu + 4096;          // bufA
    const uint32_t KV1 = smu + 4096 + 49152;  // bufB

    const int tid = threadIdx.x, lane = tid & 31, w = tid >> 5;
    const int dh = blockIdx.x, r0 = blockIdx.y * 128, bz = blockIdx.z;

    const __half* Qp = Qg + ((long)bz * S_ + r0) * D_;
    const __half* Kp = Kg + (long)bz * S_ * D_;
    const __half* Vp = Vg + (long)bz * S_ * D_ + dh * 128;
    __half* Op = Og + ((long)bz * S_ + r0) * D_ + dh * 128;
    const int* mk = mask + bz * S_;

    ((float4*)btab_s)[tid] = ((const float4*)btab)[tid];

    // ---- stage Q (64KB across bufA+bufB head), then load fragments ----
    {
        const int qr = tid >> 1, cb = (tid & 1) * 4;
        const __half* src = Qp + (long)qr * D_;
        #pragma unroll
        for (int p = 0; p < 4; p++)
            #pragma unroll
            for (int cc = 0; cc < 4; cc++)
                cp16(Qu + p * 16384 + swz(qr * 128 + (cb + cc) * 16),
                     src + p * 64 + (cb + cc) * 8);
        cp_commit();
    }
    asm volatile("cp.async.wait_group 0;" ::: "memory");
    __syncthreads();

    uint32_t qf[16][4];
    {
        const int qrow = w * 16 + (lane & 15);
        #pragma unroll
        for (int kt = 0; kt < 16; kt++)
            ldm4(qf[kt], Qu + (kt >> 2) * 16384 +
                         swz(qrow * 128 + (kt & 3) * 32 + (lane >> 4) * 16));
    }
    __syncthreads();   // all Q reads complete before KV pipeline overwrites

    const int sr = tid >> 2, sch = tid & 3;
    auto stageKV = [&](int t, int bf) {
        const __half* ks = Kp + (long)(t * 64 + sr) * D_;
        const __half* vs = Vp + (long)(t * 64 + sr) * D_;
        const uint32_t kd = bf ? KV1 : KV0;
        const uint32_t vd = kd + 32768;
        #pragma unroll
        for (int p = 0; p < 4; p++) {
            cp16(kd + p * 8192 + swz(sr * 128 + sch * 16),       ks + p * 64 + sch * 8);
            cp16(kd + p * 8192 + swz(sr * 128 + (sch + 4) * 16), ks + p * 64 + (sch + 4) * 8);
        }
        #pragma unroll
        for (int p = 0; p < 2; p++) {
            cp16(vd + p * 8192 + swz(sr * 128 + sch * 16),       vs + p * 64 + sch * 8);
            cp16(vd + p * 8192 + swz(sr * 128 + (sch + 4) * 16), vs + p * 64 + (sch + 4) * 8);
        }
    };
    stageKV(0, 0); cp_commit();

    const int g = lane >> 2, c = lane & 3;
    const int rowg = r0 + w * 16 + g;
    float oacc[16][4];
    #pragma unroll
    for (int i = 0; i < 16; i++)
        #pragma unroll
        for (int r = 0; r < 4; r++) oacc[i][r] = 0.0f;
    float l0 = 0.0f, l1 = 0.0f;

    for (int t = 0; t < 8; t++) {
        const int bf = t & 1;
        if (t < 7) {
            stageKV(t + 1, bf ^ 1);
            cp_commit();
            asm volatile("cp.async.wait_group 1;" ::: "memory");
        } else {
            asm volatile("cp.async.wait_group 0;" ::: "memory");
        }
        __syncthreads();

        // ---- S = Q K_tile^T ----
        float sacc[8][4];
        #pragma unroll
        for (int i = 0; i < 8; i++)
            #pragma unroll
            for (int r = 0; r < 4; r++) sacc[i][r] = 0.0f;
        const uint32_t Kb = bf ? KV1 : KV0;
        #pragma unroll
        for (int kt = 0; kt < 16; kt++) {
            #pragma unroll
            for (int np = 0; np < 4; np++) {
                uint32_t tt[4];
                ldm4(tt, Kb + (kt >> 2) * 8192 +
                         swz((np * 16 + (lane & 15)) * 128 + (kt & 3) * 32 + (lane >> 4) * 16));
                uint32_t b0[2] = {tt[0], tt[2]}, b1[2] = {tt[1], tt[3]};
                mma_f16(sacc[2 * np],     qf[kt], b0);
                mma_f16(sacc[2 * np + 1], qf[kt], b1);
            }
        }

        // ---- p = exp(s), masked -> 0 ; accumulate row sums ----
        float ps0 = 0.0f, ps1 = 0.0f;
        #pragma unroll
        for (int nt = 0; nt < 8; nt++) {
            const int n = t * 64 + nt * 8 + c * 2;
            const int mk0 = mk[n], mk1 = mk[n + 1];
            int rel, bk;
            rel = n - rowg;           bk = rel < 0 ? 511 - rel : rel;
            float s00 = fmaf(sacc[nt][0], 0.0625f, btab_s[bk]);
            rel = n + 1 - rowg;       bk = rel < 0 ? 511 - rel : rel;
            float s01 = fmaf(sacc[nt][1], 0.0625f, btab_s[bk]);
            rel = n - (rowg + 8);     bk = rel < 0 ? 511 - rel : rel;
            float s10 = fmaf(sacc[nt][2], 0.0625f, btab_s[bk]);
            rel = n + 1 - (rowg + 8); bk = rel < 0 ? 511 - rel : rel;
            float s11 = fmaf(sacc[nt][3], 0.0625f, btab_s[bk]);
            float p00 = mk0 ? exp2f(s00 * L2E) : 0.0f;
            float p01 = mk1 ? exp2f(s01 * L2E) : 0.0f;
            float p10 = mk0 ? exp2f(s10 * L2E) : 0.0f;
            float p11 = mk1 ? exp2f(s11 * L2E) : 0.0f;
            ps0 += p00 + p01; ps1 += p10 + p11;
            sacc[nt][0] = p00; sacc[nt][1] = p01; sacc[nt][2] = p10; sacc[nt][3] = p11;
        }
        ps0 += __shfl_xor_sync(0xffffffffu, ps0, 1);
        ps0 += __shfl_xor_sync(0xffffffffu, ps0, 2);
        ps1 += __shfl_xor_sync(0xffffffffu, ps1, 1);
        ps1 += __shfl_xor_sync(0xffffffffu, ps1, 2);
        l0 += ps0;
        l1 += ps1;

        // ---- O += P @ V_tile (P fragments straight from registers) ----
        const uint32_t Vb = (bf ? KV1 : KV0) + 32768;
        const int kb8 = (lane >> 3) & 1, nb8 = lane >> 4, li = lane & 7;
        #pragma unroll
        for (int pk = 0; pk < 4; pk++) {
            uint32_t af[4];
            af[0] = pk32(sacc[2 * pk][0],     sacc[2 * pk][1]);
            af[1] = pk32(sacc[2 * pk][2],     sacc[2 * pk][3]);
            af[2] = pk32(sacc[2 * pk + 1][0], sacc[2 * pk + 1][1]);
            af[3] = pk32(sacc[2 * pk + 1][2], sacc[2 * pk + 1][3]);
            #pragma unroll
            for (int nv = 0; nv < 8; nv++) {
                uint32_t tt[4];
                ldm4t(tt, Vb + (nv >> 2) * 8192 +
                          swz((pk * 16 + kb8 * 8 + li) * 128 + (nv & 3) * 32 + nb8 * 16));
                uint32_t b0[2] = {tt[0], tt[1]}, b1[2] = {tt[2], tt[3]};
                mma_f16(oacc[2 * nv],     af, b0);
                mma_f16(oacc[2 * nv + 1], af, b1);
            }
        }
        __syncthreads();
    }

    const float rc0 = 1.0f / l0, rc1 = 1.0f / l1;
    #pragma unroll
    for (int nt = 0; nt < 16; nt++) {
        const int col = nt * 8 + c * 2;
        st2(Op + (long)(w * 16 + g) * D_ + col,     oacc[nt][0] * rc0, oacc[nt][1] * rc0);
        st2(Op + (long)(w * 16 + g + 8) * D_ + col, oacc[nt][2] * rc1, oacc[nt][3] * rc1);
    }
}
#define FSMEM (4096 + 49152 + 49152)

// ---------------------------------------------------------------------------
// FP16 GEMM 128x128x64 — used for QKV (EPI 5) and w1+gelu (EPI 2).
// ---------------------------------------------------------------------------
template<int EPI, typename TO>
__global__ void __launch_bounds__(128, 2)
gemm_k(const __half* __restrict__ A, const __half* __restrict__ Bm,
       const float* bias, TO* C, int M, int N, int K,
       TO* C2, TO* C3, const float* bias2, const float* bias3)
{
    extern __shared__ __half smh[];
    const uint32_t smu = smem_u32(smh);

    const int tid  = threadIdx.x;
    const int lane = tid & 31;
    const int wm   = (tid >> 5) & 1;
    const int wn   = tid >> 6;
    const int bm = blockIdx.y * 128;
    const int bn = blockIdx.x * 128;

    if (EPI == 5) {
        const int sel = bn >> 8;
        if (sel == 1) { C = C2; bias = bias2; }
        else if (sel == 2) { C = C3; bias = bias3; }
    }
    const int No = (EPI == 5) ? 256 : N;

    const __half* Ap = A  + (long)(bm + tid) * K;
    const __half* Bp = Bm + (long)(bn + tid) * K;
    uint32_t dsw[8];
    #pragma unroll
    for (int j = 0; j < 8; j++) dsw[j] = swz(tid * 128 + j * 16);

    uint32_t arow[4], brow[4];
    #pragma unroll
    for (int i = 0; i < 4; i++) {
        arow[i] = (wm * 64 + i * 16 + (lane & 15)) * 128 + (lane >> 4) * 16;
        brow[i] = (wn * 64 + i * 16 + (lane & 15)) * 128 + (lane >> 4) * 16;
    }
    const int g = lane >> 2;
    const int c = lane & 3;

    float acc[4][8][4];
    #pragma unroll
    for (int i = 0; i < 4; i++)
        #pragma unroll
        for (int j = 0; j < 8; j++)
            #pragma unroll
            for (int r = 0; r < 4; r++) acc[i][j][r] = 0.0f;

    const int nst = K >> 6;

    #pragma unroll
    for (int j = 0; j < 8; j++) {
        cp16(smu + dsw[j],         Ap + j * 8);
        cp16(smu + 16384 + dsw[j], Bp + j * 8);
    }
    cp_commit();

    int buf = 0;
    for (int s = 0; s < nst; s++) {
        if (s + 1 < nst) {
            const int kn = (s + 1) << 6;
            const uint32_t base = smu + (buf ^ 1) * 32768;
            #pragma unroll
            for (int j = 0; j < 8; j++) {
                cp16(base + dsw[j],         Ap + kn + j * 8);
                cp16(base + 16384 + dsw[j], Bp + kn + j * 8);
            }
            cp_commit();
            asm volatile("cp.async.wait_group 1;" ::: "memory");
        } else {
            asm volatile("cp.async.wait_group 0;" ::: "memory");
        }
        __syncthreads();

        const uint32_t Au = smu + buf * 32768;
        const uint32_t Bu = Au + 16384;
        #pragma unroll
        for (int kb = 0; kb < 4; kb++) {
            uint32_t af[4][4];
            uint32_t bf[8][2];
            #pragma unroll
            for (int ma = 0; ma < 4; ma++)
                ldm4(af[ma], Au + swz(arow[ma] + kb * 32));
            #pragma unroll
            for (int np = 0; np < 4; np++) {
                uint32_t t[4];
                ldm4(t, Bu + swz(brow[np] + kb * 32));
                bf[2*np][0]   = t[0];
                bf[2*np+1][0] = t[1];
                bf[2*np][1]   = t[2];
                bf[2*np+1][1] = t[3];
            }
            #pragma unroll
            for (int ma = 0; ma < 4; ma++)
                #pragma unroll
                for (int nb = 0; nb < 8; nb++)
                    mma_f16(acc[ma][nb], af[ma], bf[nb]);
        }
        __syncthreads();
        buf ^= 1;
    }

    #pragma unroll
    for (int nb = 0; nb < 8; nb++) {
        const int col  = bn + wn * 64 + nb * 8 + c * 2;
        const int colo = (EPI == 5) ? (col & 255) : col;
        float2 bv = *(const float2*)(bias + colo);

        #pragma unroll
        for (int ma = 0; ma < 4; ma++) {
            const int r0 = bm + wm * 64 + ma * 16 + g;
            const int r1 = r0 + 8;
            float d0 = acc[ma][nb][0] + bv.x, d1 = acc[ma][nb][1] + bv.y;
            float d2 = acc[ma][nb][2] + bv.x, d3 = acc[ma][nb][3] + bv.y;
            if (EPI == 2) {
                d0 = 0.5f * d0 * (1.0f + erff(d0 * 0.70710678118654752f));
                d1 = 0.5f * d1 * (1.0f + erff(d1 * 0.70710678118654752f));
                d2 = 0.5f * d2 * (1.0f + erff(d2 * 0.70710678118654752f));
                d3 = 0.5f * d3 * (1.0f + erff(d3 * 0.70710678118654752f));
            }
            st2(C + (long)r0 * No + colo, d0, d1);
            st2(C + (long)r1 * No + colo, d2, d3);
        }
    }
}
#define GSMEM 65536

// ---------------------------------------------------------------------------
// WIDE GEMM 128x256x64: 256 threads (8 warps: wm=w&1, wn=w>>1), warp 64x64.
// CTA computes full output rows -> LayerNorm fused in epilogue.
// MODE 6 (wo):  t = A@B + bias; x = h32 + LN_{g1,b1}(t); xo=x; C16=LN_{g2,b2}(x)
// MODE 7 (w2):  x = res32 + A@B + bias; xo=x; if g1: H=LN_{g1,b1}(x) -> h16,h32
// smem: 2 x (A 16KB + B 32KB) = 96KB; epilogue reduction reuses first 4KB.
// ---------------------------------------------------------------------------
template<int MODE>
__global__ void __launch_bounds__(256, 1)
gemmw_k(const __half* __restrict__ A, const __half* __restrict__ Bm,
        const float* __restrict__ bias, const float* __restrict__ res32,
        float* __restrict__ xo, __half* __restrict__ out16,
        float* __restrict__ out32,
        const float* __restrict__ g1, const float* __restrict__ b1v,
        const float* __restrict__ g2, const float* __restrict__ b2v)
{
    extern __shared__ __half smh[];
    const uint32_t smu = smem_u32(smh);
    float* red = (float*)smh;          // [128][4] sums + [128][4] sumsq = 4KB

    const int tid  = threadIdx.x;
    const int lane = tid & 31;
    const int w    = tid >> 5;
    const int wm   = w & 1;
    const int wn   = w >> 1;           // 0..3
    const int bm   = blockIdx.y * 128;

    // staging: A row = tid>>1 (4 chunks), B row = tid (8 chunks)
    const __half* Ap = A  + (long)(bm + (tid >> 1)) * D_ + (tid & 1) * 32;
    const __half* Bp = Bm + (long)tid * D_;
    uint32_t adsw[4], bdsw[8];
    #pragma unroll
    for (int j = 0; j < 4; j++)
        adsw[j] = swz((tid >> 1) * 128 + ((tid & 1) * 4 + j) * 16);
    #pragma unroll
    for (int j = 0; j < 8; j++) bdsw[j] = 16384 + swz(tid * 128 + j * 16);

    const int g = lane >> 2;
    const int c = lane & 3;

    float acc[4][8][4];
    #pragma unroll
    for (int i = 0; i < 4; i++)
        #pragma unroll
        for (int j = 0; j < 8; j++)
            #pragma unroll
            for (int r = 0; r < 4; r++) acc[i][j][r] = 0.0f;

    // prologue
    #pragma unroll
    for (int j = 0; j < 4; j++) cp16(smu + adsw[j], Ap + j * 8);
    #pragma unroll
    for (int j = 0; j < 8; j++) cp16(smu + bdsw[j], Bp + j * 8);
    cp_commit();

    int buf = 0;
    #pragma unroll
    for (int s = 0; s < 4; s++) {
        if (s < 3) {
            const int kn = (s + 1) << 6;
            const uint32_t base = smu + (buf ^ 1) * 49152;
            #pragma unroll
            for (int j = 0; j < 4; j++) cp16(base + adsw[j], Ap + kn + j * 8);
            #pragma unroll
            for (int j = 0; j < 8; j++) cp16(base + bdsw[j], Bp + kn + j * 8);
            cp_commit();
            asm volatile("cp.async.wait_group 1;" ::: "memory");
        } else {
            asm volatile("cp.async.wait_group 0;" ::: "memory");
        }
        __syncthreads();

        const uint32_t base = smu + buf * 49152;
        #pragma unroll
        for (int kb = 0; kb < 4; kb++) {
            uint32_t af[4][4];
            uint32_t bf[8][2];
            #pragma unroll
            for (int ma = 0; ma < 4; ma++)
                ldm4(af[ma], base +
                     swz((wm * 64 + ma * 16 + (lane & 15)) * 128 + kb * 32 + (lane >> 4) * 16));
            #pragma unroll
            for (int np = 0; np < 4; np++) {
                uint32_t t[4];
                ldm4(t, base + 16384 +
                        swz((wn * 64 + np * 16 + (lane & 15)) * 128 + kb * 32 + (lane >> 4) * 16));
                bf[2*np][0]   = t[0];
                bf[2*np+1][0] = t[1];
                bf[2*np][1]   = t[2];
                bf[2*np+1][1] = t[3];
            }
            #pragma unroll
            for (int ma = 0; ma < 4; ma++)
                #pragma unroll
                for (int nb = 0; nb < 8; nb++)
                    mma_f16(acc[ma][nb], af[ma], bf[nb]);
        }
        __syncthreads();
        buf ^= 1;
    }

    // ================= epilogue with fused LayerNorm(s) =================
    const int colb = wn * 64 + c * 2;      // + nb*8
    float2 biasv[8];
    #pragma unroll
    for (int nb = 0; nb < 8; nb++) biasv[nb] = *(const float2*)(bias + colb + nb * 8);

    #pragma unroll
    for (int ma = 0; ma < 4; ma++) {
        const long r0 = bm + wm * 64 + ma * 16 + g;
        #pragma unroll
        for (int nb = 0; nb < 8; nb++) {
            acc[ma][nb][0] += biasv[nb].x; acc[ma][nb][1] += biasv[nb].y;
            acc[ma][nb][2] += biasv[nb].x; acc[ma][nb][3] += biasv[nb].y;
            if (MODE == 7) {
                float2 ra = *(const float2*)(res32 + r0 * D_ + colb + nb * 8);
                float2 rb = *(const float2*)(res32 + (r0 + 8) * D_ + colb + nb * 8);
                acc[ma][nb][0] += ra.x; acc[ma][nb][1] += ra.y;
                acc[ma][nb][2] += rb.x; acc[ma][nb][3] += rb.y;
            }
        }
    }

    float mean0[4], inv0[4], mean1[4], inv1[4];
    auto reduce_rows = [&]() {
        #pragma unroll
        for (int ma = 0; ma < 4; ma++) {
            float s0 = 0, q0 = 0, s1 = 0, q1 = 0;
            #pragma unroll
            for (int nb = 0; nb < 8; nb++) {
                s0 += acc[ma][nb][0] + acc[ma][nb][1];
                q0 += acc[ma][nb][0] * acc[ma][nb][0] + acc[ma][nb][1] * acc[ma][nb][1];
                s1 += acc[ma][nb][2] + acc[ma][nb][3];
                q1 += acc[ma][nb][2] * acc[ma][nb][2] + acc[ma][nb][3] * acc[ma][nb][3];
            }
            s0 += __shfl_xor_sync(0xffffffffu, s0, 1); s0 += __shfl_xor_sync(0xffffffffu, s0, 2);
            q0 += __shfl_xor_sync(0xffffffffu, q0, 1); q0 += __shfl_xor_sync(0xffffffffu, q0, 2);
            s1 += __shfl_xor_sync(0xffffffffu, s1, 1); s1 += __shfl_xor_sync(0xffffffffu, s1, 2);
            q1 += __shfl_xor_sync(0xffffffffu, q1, 1); q1 += __shfl_xor_sync(0xffffffffu, q1, 2);
            if (c == 0) {
                const int r = wm * 64 + ma * 16 + g;
                red[r * 4 + wn]       = s0;  red[512 + r * 4 + wn]       = q0;
                red[(r + 8) * 4 + wn] = s1;  red[512 + (r + 8) * 4 + wn] = q1;
            }
        }
        __syncthreads();
        #pragma unroll
        for (int ma = 0; ma < 4; ma++) {
            const int r = wm * 64 + ma * 16 + g;
            float s0 = red[r*4] + red[r*4+1] + red[r*4+2] + red[r*4+3];
            float q0 = red[512+r*4] + red[512+r*4+1] + red[512+r*4+2] + red[512+r*4+3];
            float s1 = red[(r+8)*4] + red[(r+8)*4+1] + red[(r+8)*4+2] + red[(r+8)*4+3];
            float q1 = red[512+(r+8)*4] + red[512+(r+8)*4+1] + red[512+(r+8)*4+2] + red[512+(r+8)*4+3];
            mean0[ma] = s0 * (1.0f / 256.0f);
            inv0[ma]  = rsqrtf(q0 * (1.0f / 256.0f) - mean0[ma] * mean0[ma] + 1e-5f);
            mean1[ma] = s1 * (1.0f / 256.0f);
            inv1[ma]  = rsqrtf(q1 * (1.0f / 256.0f) - mean1[ma] * mean1[ma] + 1e-5f);
        }
        __syncthreads();
    };

    __syncthreads();
    if (MODE == 7 && g1 == nullptr) {
        #pragma unroll
        for (int ma = 0; ma < 4; ma++) {
            const long r0 = bm + wm * 64 + ma * 16 + g;
            #pragma unroll
            for (int nb = 0; nb < 8; nb++) {
                st2(xo + r0 * D_ + colb + nb * 8,       acc[ma][nb][0], acc[ma][nb][1]);
                st2(xo + (r0 + 8) * D_ + colb + nb * 8, acc[ma][nb][2], acc[ma][nb][3]);
            }
        }
        return;
    }

    reduce_rows();   // stats of t (MODE 6) or x (MODE 7)

    float2 g1v[8], b1vv[8];
    #pragma unroll
    for (int nb = 0; nb < 8; nb++) {
        g1v[nb]  = *(const float2*)(g1 + colb + nb * 8);
        b1vv[nb] = *(const float2*)(b1v + colb + nb * 8);
    }

    if (MODE == 7) {
        #pragma unroll
        for (int ma = 0; ma < 4; ma++) {
            const long r0 = bm + wm * 64 + ma * 16 + g;
            #pragma unroll
            for (int nb = 0; nb < 8; nb++) {
                const int cc = colb + nb * 8;
                float x0 = acc[ma][nb][0], x1 = acc[ma][nb][1];
                float x2 = acc[ma][nb][2], x3 = acc[ma][nb][3];
                st2(xo + r0 * D_ + cc, x0, x1);
                st2(xo + (r0 + 8) * D_ + cc, x2, x3);
                float h0 = (x0 - mean0[ma]) * inv0[ma] * g1v[nb].x + b1vv[nb].x;
                float h1 = (x1 - mean0[ma]) * inv0[ma] * g1v[nb].y + b1vv[nb].y;
                float h2 = (x2 - mean1[ma]) * inv1[ma] * g1v[nb].x + b1vv[nb].x;
                float h3 = (x3 - mean1[ma]) * inv1[ma] * g1v[nb].y + b1vv[nb].y;
                st2(out32 + r0 * D_ + cc, h0, h1);
                st2(out32 + (r0 + 8) * D_ + cc, h2, h3);
                st2(out16 + r0 * D_ + cc, h0, h1);
                st2(out16 + (r0 + 8) * D_ + cc, h2, h3);
            }
        }
        return;
    }

    // MODE 6: x = h32 + LN(t); second LN for C16
    #pragma unroll
    for (int ma = 0; ma < 4; ma++) {
        const long r0 = bm + wm * 64 + ma * 16 + g;
        #pragma unroll
        for (int nb = 0; nb < 8; nb++) {
            const int cc = colb + nb * 8;
            float2 ha = *(const float2*)(res32 + r0 * D_ + cc);
            float2 hb = *(const float2*)(res32 + (r0 + 8) * D_ + cc);
            acc[ma][nb][0] = ha.x + (acc[ma][nb][0] - mean0[ma]) * inv0[ma] * g1v[nb].x + b1vv[nb].x;
            acc[ma][nb][1] = ha.y + (acc[ma][nb][1] - mean0[ma]) * inv0[ma] * g1v[nb].y + b1vv[nb].y;
            acc[ma][nb][2] = hb.x + (acc[ma][nb][2] - mean1[ma]) * inv1[ma] * g1v[nb].x + b1vv[nb].x;
            acc[ma][nb][3] = hb.y + (acc[ma][nb][3] - mean1[ma]) * inv1[ma] * g1v[nb].y + b1vv[nb].y;
        }
    }
    reduce_rows();   // stats of x

    #pragma unroll
    for (int nb = 0; nb < 8; nb++) {
        g1v[nb]  = *(const float2*)(g2 + colb + nb * 8);
        b1vv[nb] = *(const float2*)(b2v + colb + nb * 8);
    }
    #pragma unroll
    for (int ma = 0; ma < 4; ma++) {
        const long r0 = bm + wm * 64 + ma * 16 + g;
        #pragma unroll
        for (int nb = 0; nb < 8; nb++) {
            const int cc = colb + nb * 8;
            float x0 = acc[ma][nb][0], x1 = acc[ma][nb][1];
            float x2 = acc[ma][nb][2], x3 = acc[ma][nb][3];
            st2(xo + r0 * D_ + cc, x0, x1);
            st2(xo + (r0 + 8) * D_ + cc, x2, x3);
            float c0 = (x0 - mean0[ma]) * inv0[ma] * g1v[nb].x + b1vv[nb].x;
            float c1 = (x1 - mean0[ma]) * inv0[ma] * g1v[nb].y + b1vv[nb].y;
            float c2 = (x2 - mean1[ma]) * inv1[ma] * g1v[nb].x + b1vv[nb].x;
            float c3 = (x3 - mean1[ma]) * inv1[ma] * g1v[nb].y + b1vv[nb].y;
            st2(out16 + r0 * D_ + cc, c0, c1);
            st2(out16 + (r0 + 8) * D_ + cc, c2, c3);
        }
    }
}
#define WSMEM 98304

// ---------------------------------------------------------------------------
// Launcher
// ---------------------------------------------------------------------------
extern "C" void kernel_launch(void* const* d_in, const int* in_sizes, int n_in,
                              void* d_out, int out_size)
{
    const float* x    = (const float*)d_in[0];
    const int*   mask = (const int*)  d_in[1];
    const float* btab = (const float*)d_in[2];
    const float* ln_g = (const float*)d_in[3];
    const float* ln_b = (const float*)d_in[4];
    const float* wq   = (const float*)d_in[5];
    const float* bq   = (const float*)d_in[6];
    const float* wk   = (const float*)d_in[7];
    const float* bk   = (const float*)d_in[8];
    const float* wv   = (const float*)d_in[9];
    const float* bv   = (const float*)d_in[10];
    const float* wo   = (const float*)d_in[11];
    const float* bo   = (const float*)d_in[12];
    const float* cmg  = (const float*)d_in[13];
    const float* cmb  = (const float*)d_in[14];
    const float* w1   = (const float*)d_in[15];
    const float* b1   = (const float*)d_in[16];
    const float* w2   = (const float*)d_in[17];
    const float* b2   = (const float*)d_in[18];
    float* xo = (float*)d_out;

    __half *H16, *Q16, *K16, *V16, *O16, *C16, *F16, *WT, *WQKV;
    float *H32;
    cudaGetSymbolAddress((void**)&H16,  g_H16);
    cudaGetSymbolAddress((void**)&Q16,  g_Q16);
    cudaGetSymbolAddress((void**)&K16,  g_K16);
    cudaGetSymbolAddress((void**)&V16,  g_V16);
    cudaGetSymbolAddress((void**)&O16,  g_O16);
    cudaGetSymbolAddress((void**)&C16,  g_C16);
    cudaGetSymbolAddress((void**)&F16,  g_F16);
    cudaGetSymbolAddress((void**)&WT,   g_WT16);
    cudaGetSymbolAddress((void**)&WQKV, g_WQKV);
    cudaGetSymbolAddress((void**)&H32,  g_H32);

    cudaFuncSetAttribute(gemm_k<5, __half>, cudaFuncAttributeMaxDynamicSharedMemorySize, GSMEM);
    cudaFuncSetAttribute(gemm_k<2, __half>, cudaFuncAttributeMaxDynamicSharedMemorySize, GSMEM);
    cudaFuncSetAttribute(gemmw_k<6>, cudaFuncAttributeMaxDynamicSharedMemorySize, WSMEM);
    cudaFuncSetAttribute(gemmw_k<7>, cudaFuncAttributeMaxDynamicSharedMemorySize, WSMEM);
    cudaFuncSetAttribute(flash_k, cudaFuncAttributeMaxDynamicSharedMemorySize, FSMEM);

    // one-time weight transposes (fp32 -> fp16, transposed)
    const dim3 trWg(8, 8, 3), trB(32, 8);
    trW_k<<<trWg, trB>>>(wq, WQKV + 0L * WSZ, D_, D_, 3L * WSZ);
    trW_k<<<trWg, trB>>>(wk, WQKV + 1L * WSZ, D_, D_, 3L * WSZ);
    trW_k<<<trWg, trB>>>(wv, WQKV + 2L * WSZ, D_, D_, 3L * WSZ);
    trW_k<<<trWg, trB>>>(wo, WT + 0L * 3 * WSZ, D_, D_, WSZ);
    trW_k<<<trWg, trB>>>(w1, WT + 1L * 3 * WSZ, D_, D_, WSZ);
    trW_k<<<trWg, trB>>>(w2, WT + 2L * 3 * WSZ, D_, D_, WSZ);

    const dim3 gQKV(6, ROWS / 128, 1);
    const dim3 gProj(D_ / 128, ROWS / 128, 1);
    const dim3 gWide(1, ROWS / 128, 1);          // 256 CTAs (M=128 tiles)
    const dim3 gFlash(2, S_ / 128, B_);
    const int  rowBlocks = ROWS / 8;

    // layer-0 input LN
    ln_k<<<rowBlocks, 256>>>(x, ln_g, ln_b, H16, H32, ROWS);

    for (int j = 0; j < 3; j++) {
        const float* gj = ln_g + j * D_;
        const float* bj = ln_b + j * D_;
        const __half* wqkvT = WQKV + (long)j * 3 * WSZ;
        const __half* woT   = WT + (0L * 3 + j) * WSZ;
        const __half* w1T   = WT + (1L * 3 + j) * WSZ;
        const __half* w2T   = WT + (2L * 3 + j) * WSZ;

        // q,k,v = h @ {wq,wk,wv} + bias (fused, routed)
        gemm_k<5, __half><<<gQKV, 128, GSMEM>>>(H16, wqkvT, bq + j * D_, Q16,
                                                ROWS, 768, D_,
                                                K16, V16, bk + j * D_, bv + j * D_);

        // o = attention(q, k, v)
        flash_k<<<gFlash, 256, FSMEM>>>(Q16, K16, V16, mask, btab, O16);

        // x = h + LN(o@wo+bo); c = LN_cm(x)   (fused wide GEMM)
        gemmw_k<6><<<gWide, 256, WSMEM>>>(O16, woT, bo + j * D_, H32,
                                          xo, C16, nullptr,
                                          gj, bj, cmg + j * D_, cmb + j * D_);

        // f = gelu(c @ w1 + b1)
        gemm_k<2, __half><<<gProj, 128, GSMEM>>>(C16, w1T, b1 + j * D_, F16,
                                                 ROWS, D_, D_,
                                                 (__half*)nullptr, (__half*)nullptr, nullptr, nullptr);

        // x = x + f@w2 + b2 ; h_next = LN(x) (layers 0,1)
        const bool last = (j == 2);
        gemmw_k<7><<<gWide, 256, WSMEM>>>(F16, w2T, b2 + j * D_, xo,
                                          xo, last ? nullptr : H16,
                                          last ? nullptr : H32,
                                          last ? nullptr : ln_g + (j + 1) * D_,
                                          last ? nullptr : ln_b + (j + 1) * D_,
                                          nullptr, nullptr);
    }
}

// round 14
// speedup vs baseline: 1.1724x; 1.1724x over previous
#include <cuda_runtime.h>
#include <cuda_fp16.h>
#include <math.h>
#include <stdint.h>

// Problem dims (fixed)
#define B_   64
#define S_   512
#define D_   256
#define ROWS (B_ * S_)          // 32768
#define WSZ  (D_ * D_)          // 65536 per-layer weight size
#define L2E  1.4426950408889634f

// ---------------------------------------------------------------------------
// Scratch (device globals; no allocation allowed)
// ---------------------------------------------------------------------------
__device__ __half g_H16[ROWS * D_];
__device__ __half g_Q16[ROWS * D_];
__device__ __half g_K16[ROWS * D_];
__device__ __half g_V16[ROWS * D_];
__device__ __half g_O16[ROWS * D_];
__device__ __half g_C16[ROWS * D_];
__device__ __half g_F16[ROWS * D_];
__device__ __half g_WT16[3 * 3 * WSZ];        // wo,w1,w2 transposed fp16
__device__ __half g_WQKV[3 * 3 * WSZ];        // per-layer [768][256] fp16
__device__ float  g_H32[ROWS * D_];           // LN(x) fp32 (residual use)

// ---------------------------------------------------------------------------
// helpers
// ---------------------------------------------------------------------------
__device__ __forceinline__ uint32_t smem_u32(const void* p) {
    uint32_t a;
    asm("{ .reg .u64 t; cvta.to.shared.u64 t, %1; cvt.u32.u64 %0, t; }"
        : "=r"(a) : "l"(p));
    return a;
}
__device__ __forceinline__ uint32_t swz(uint32_t byte) {   // SW128
    return byte ^ ((byte >> 3) & 0x70);
}
__device__ __forceinline__ void cp16(uint32_t dst, const void* src) {
    asm volatile("cp.async.cg.shared.global [%0], [%1], 16;"
                 :: "r"(dst), "l"(src) : "memory");
}
__device__ __forceinline__ void cp_commit() {
    asm volatile("cp.async.commit_group;" ::: "memory");
}
__device__ __forceinline__ void ldm4(uint32_t* r, uint32_t a) {
    asm volatile("ldmatrix.sync.aligned.m8n8.x4.shared.b16 {%0,%1,%2,%3}, [%4];"
                 : "=r"(r[0]), "=r"(r[1]), "=r"(r[2]), "=r"(r[3]) : "r"(a));
}
__device__ __forceinline__ void ldm4t(uint32_t* r, uint32_t a) {
    asm volatile("ldmatrix.sync.aligned.m8n8.x4.trans.shared.b16 {%0,%1,%2,%3}, [%4];"
                 : "=r"(r[0]), "=r"(r[1]), "=r"(r[2]), "=r"(r[3]) : "r"(a));
}
__device__ __forceinline__ void mma_f16(float* d, const uint32_t* a, const uint32_t* b) {
    asm volatile(
        "mma.sync.aligned.m16n8k16.row.col.f32.f16.f16.f32 "
        "{%0,%1,%2,%3}, {%4,%5,%6,%7}, {%8,%9}, {%0,%1,%2,%3};"
        : "+f"(d[0]), "+f"(d[1]), "+f"(d[2]), "+f"(d[3])
        : "r"(a[0]), "r"(a[1]), "r"(a[2]), "r"(a[3]), "r"(b[0]), "r"(b[1]));
}
__device__ __forceinline__ uint32_t pk32(float a, float b) {
    __half2 h = __floats2half2_rn(a, b);
    return *reinterpret_cast<uint32_t*>(&h);
}
__device__ __forceinline__ float ex2(float x) {    // single MUFU.EX2
    float r;
    asm("ex2.approx.f32 %0, %1;" : "=f"(r) : "f"(x));
    return r;
}
__device__ __forceinline__ float frcp(float x) {   // single MUFU.RCP
    float r;
    asm("rcp.approx.f32 %0, %1;" : "=f"(r) : "f"(x));
    return r;
}
__device__ __forceinline__ void st2(float* p, float a, float b) {
    *(float2*)p = make_float2(a, b);
}
__device__ __forceinline__ void st2(__half* p, float a, float b) {
    *(__half2*)p = __floats2half2_rn(a, b);
}

// ---------------------------------------------------------------------------
// Weight transpose: float in -> half out, out[c][r] = in[r][c]; z-stride param
// ---------------------------------------------------------------------------
__global__ void trW_k(const float* __restrict__ in, __half* __restrict__ out,
                      int rows, int cols, long ostride)
{
    __shared__ float t[32][33];
    in  += blockIdx.z * (long)rows * cols;
    out += blockIdx.z * ostride;
    const int r0 = blockIdx.y * 32, c0 = blockIdx.x * 32;
    const int tx = threadIdx.x, ty = threadIdx.y;
    #pragma unroll
    for (int i = 0; i < 32; i += 8)
        t[ty + i][tx] = in[(long)(r0 + ty + i) * cols + c0 + tx];
    __syncthreads();
    #pragma unroll
    for (int i = 0; i < 32; i += 8)
        out[(long)(c0 + ty + i) * rows + r0 + tx] = __float2half_rn(t[tx][ty + i]);
}

// ---------------------------------------------------------------------------
// LayerNorm (used once, layer 0 input): one warp per row -> H16 + H32
// ---------------------------------------------------------------------------
__global__ void ln_k(const float* __restrict__ in,
                     const float* __restrict__ g, const float* __restrict__ b,
                     __half* __restrict__ out16, float* __restrict__ out32, int rows)
{
    int warp = (blockIdx.x * blockDim.x + threadIdx.x) >> 5;
    int lane = threadIdx.x & 31;
    if (warp >= rows) return;

    const float4* x4 = (const float4*)(in + (long)warp * D_);
    float4 v0 = x4[lane];
    float4 v1 = x4[lane + 32];

    float s = v0.x + v0.y + v0.z + v0.w + v1.x + v1.y + v1.z + v1.w;
    #pragma unroll
    for (int o = 16; o; o >>= 1) s += __shfl_xor_sync(0xffffffffu, s, o);
    float mean = s * (1.0f / 256.0f);

    float d0x = v0.x - mean, d0y = v0.y - mean, d0z = v0.z - mean, d0w = v0.w - mean;
    float d1x = v1.x - mean, d1y = v1.y - mean, d1z = v1.z - mean, d1w = v1.w - mean;
    float q = d0x*d0x + d0y*d0y + d0z*d0z + d0w*d0w
            + d1x*d1x + d1y*d1y + d1z*d1z + d1w*d1w;
    #pragma unroll
    for (int o = 16; o; o >>= 1) q += __shfl_xor_sync(0xffffffffu, q, o);
    float inv = rsqrtf(q * (1.0f / 256.0f) + 1e-5f);

    const float4* g4 = (const float4*)g;
    const float4* b4 = (const float4*)b;
    float4 gv0 = g4[lane], gv1 = g4[lane + 32];
    float4 bv0 = b4[lane], bv1 = b4[lane + 32];

    float4 o0, o1;
    o0.x = d0x * inv * gv0.x + bv0.x;  o0.y = d0y * inv * gv0.y + bv0.y;
    o0.z = d0z * inv * gv0.z + bv0.z;  o0.w = d0w * inv * gv0.w + bv0.w;
    o1.x = d1x * inv * gv1.x + bv1.x;  o1.y = d1y * inv * gv1.y + bv1.y;
    o1.z = d1z * inv * gv1.z + bv1.z;  o1.w = d1w * inv * gv1.w + bv1.w;

    float4* out4 = (float4*)(out32 + (long)warp * D_);
    out4[lane]      = o0;
    out4[lane + 32] = o1;
    __half2* oh = (__half2*)(out16 + (long)warp * D_);
    oh[lane * 2]            = __floats2half2_rn(o0.x, o0.y);
    oh[lane * 2 + 1]        = __floats2half2_rn(o0.z, o0.w);
    oh[(lane + 32) * 2]     = __floats2half2_rn(o1.x, o1.y);
    oh[(lane + 32) * 2 + 1] = __floats2half2_rn(o1.z, o1.w);
}

// ---------------------------------------------------------------------------
// Fused flash attention (round-11 shape: 164KB smem, no occupancy clause).
// Softmax without max-subtraction (exact identity here; logits are O(1)).
// exp via single-MUFU ex2.approx.
// ---------------------------------------------------------------------------
__global__ void __launch_bounds__(256)
flash_k(const __half* __restrict__ Qg, const __half* __restrict__ Kg,
        const __half* __restrict__ Vg, const int* __restrict__ mask,
        const float* __restrict__ btab, __half* __restrict__ Og)
{
    extern __shared__ char sm[];
    const uint32_t smu = smem_u32(sm);
    float* btab_s = (float*)sm;
    const uint32_t Qu = smu + 4096;
    const uint32_t Ku = Qu + 65536;
    const uint32_t Vu = Ku + 65536;

    const int tid = threadIdx.x, lane = tid & 31, w = tid >> 5;
    const int dh = blockIdx.x, r0 = blockIdx.y * 128, bz = blockIdx.z;

    const __half* Qp = Qg + ((long)bz * S_ + r0) * D_;
    const __half* Kp = Kg + (long)bz * S_ * D_;
    const __half* Vp = Vg + (long)bz * S_ * D_ + dh * 128;
    __half* Op = Og + ((long)bz * S_ + r0) * D_ + dh * 128;
    const int* mk = mask + bz * S_;

    ((float4*)btab_s)[tid] = ((const float4*)btab)[tid];

    {
        const int qr = tid >> 1, cb = (tid & 1) * 4;
        const __half* src = Qp + (long)qr * D_;
        #pragma unroll
        for (int p = 0; p < 4; p++)
            #pragma unroll
            for (int cc = 0; cc < 4; cc++)
                cp16(Qu + p * 16384 + swz(qr * 128 + (cb + cc) * 16),
                     src + p * 64 + (cb + cc) * 8);
        cp_commit();
    }

    const int sr = tid >> 2, sch = tid & 3;
    auto stageKV = [&](int t, int bf) {
        const __half* ks = Kp + (long)(t * 64 + sr) * D_;
        const __half* vs = Vp + (long)(t * 64 + sr) * D_;
        const uint32_t kd = Ku + bf * 32768;
        const uint32_t vd = Vu + bf * 16384;
        #pragma unroll
        for (int p = 0; p < 4; p++) {
            cp16(kd + p * 8192 + swz(sr * 128 + sch * 16),       ks + p * 64 + sch * 8);
            cp16(kd + p * 8192 + swz(sr * 128 + (sch + 4) * 16), ks + p * 64 + (sch + 4) * 8);
        }
        #pragma unroll
        for (int p = 0; p < 2; p++) {
            cp16(vd + p * 8192 + swz(sr * 128 + sch * 16),       vs + p * 64 + sch * 8);
            cp16(vd + p * 8192 + swz(sr * 128 + (sch + 4) * 16), vs + p * 64 + (sch + 4) * 8);
        }
    };
    stageKV(0, 0); cp_commit();

    asm volatile("cp.async.wait_group 1;" ::: "memory");
    __syncthreads();
    uint32_t qf[16][4];
    {
        const int qrow = w * 16 + (lane & 15);
        #pragma unroll
        for (int kt = 0; kt < 16; kt++)
            ldm4(qf[kt], Qu + (kt >> 2) * 16384 +
                         swz(qrow * 128 + (kt & 3) * 32 + (lane >> 4) * 16));
    }

    const int g = lane >> 2, c = lane & 3;
    const int rowg = r0 + w * 16 + g;
    float oacc[16][4];
    #pragma unroll
    for (int i = 0; i < 16; i++)
        #pragma unroll
        for (int r = 0; r < 4; r++) oacc[i][r] = 0.0f;
    float l0 = 0.0f, l1 = 0.0f;

    for (int t = 0; t < 8; t++) {
        const int bf = t & 1;
        if (t < 7) {
            stageKV(t + 1, bf ^ 1);
            cp_commit();
            asm volatile("cp.async.wait_group 1;" ::: "memory");
        } else {
            asm volatile("cp.async.wait_group 0;" ::: "memory");
        }
        __syncthreads();

        // ---- S = Q K_tile^T ----
        float sacc[8][4];
        #pragma unroll
        for (int i = 0; i < 8; i++)
            #pragma unroll
            for (int r = 0; r < 4; r++) sacc[i][r] = 0.0f;
        const uint32_t Kb = Ku + bf * 32768;
        #pragma unroll
        for (int kt = 0; kt < 16; kt++) {
            #pragma unroll
            for (int np = 0; np < 4; np++) {
                uint32_t tt[4];
                ldm4(tt, Kb + (kt >> 2) * 8192 +
                         swz((np * 16 + (lane & 15)) * 128 + (kt & 3) * 32 + (lane >> 4) * 16));
                uint32_t b0[2] = {tt[0], tt[2]}, b1[2] = {tt[1], tt[3]};
                mma_f16(sacc[2 * np],     qf[kt], b0);
                mma_f16(sacc[2 * np + 1], qf[kt], b1);
            }
        }

        // ---- p = exp(s), masked -> 0 ; accumulate row sums ----
        float ps0 = 0.0f, ps1 = 0.0f;
        #pragma unroll
        for (int nt = 0; nt < 8; nt++) {
            const int n = t * 64 + nt * 8 + c * 2;
            const int mk0 = mk[n], mk1 = mk[n + 1];
            int rel, bk;
            rel = n - rowg;           bk = rel < 0 ? 511 - rel : rel;
            float s00 = fmaf(sacc[nt][0], 0.0625f, btab_s[bk]);
            rel = n + 1 - rowg;       bk = rel < 0 ? 511 - rel : rel;
            float s01 = fmaf(sacc[nt][1], 0.0625f, btab_s[bk]);
            rel = n - (rowg + 8);     bk = rel < 0 ? 511 - rel : rel;
            float s10 = fmaf(sacc[nt][2], 0.0625f, btab_s[bk]);
            rel = n + 1 - (rowg + 8); bk = rel < 0 ? 511 - rel : rel;
            float s11 = fmaf(sacc[nt][3], 0.0625f, btab_s[bk]);
            float p00 = mk0 ? ex2(s00 * L2E) : 0.0f;
            float p01 = mk1 ? ex2(s01 * L2E) : 0.0f;
            float p10 = mk0 ? ex2(s10 * L2E) : 0.0f;
            float p11 = mk1 ? ex2(s11 * L2E) : 0.0f;
            ps0 += p00 + p01; ps1 += p10 + p11;
            sacc[nt][0] = p00; sacc[nt][1] = p01; sacc[nt][2] = p10; sacc[nt][3] = p11;
        }
        ps0 += __shfl_xor_sync(0xffffffffu, ps0, 1);
        ps0 += __shfl_xor_sync(0xffffffffu, ps0, 2);
        ps1 += __shfl_xor_sync(0xffffffffu, ps1, 1);
        ps1 += __shfl_xor_sync(0xffffffffu, ps1, 2);
        l0 += ps0;
        l1 += ps1;

        // ---- O += P @ V_tile (P fragments straight from registers) ----
        const uint32_t Vb = Vu + bf * 16384;
        const int kb8 = (lane >> 3) & 1, nb8 = lane >> 4, li = lane & 7;
        #pragma unroll
        for (int pk = 0; pk < 4; pk++) {
            uint32_t af[4];
            af[0] = pk32(sacc[2 * pk][0],     sacc[2 * pk][1]);
            af[1] = pk32(sacc[2 * pk][2],     sacc[2 * pk][3]);
            af[2] = pk32(sacc[2 * pk + 1][0], sacc[2 * pk + 1][1]);
            af[3] = pk32(sacc[2 * pk + 1][2], sacc[2 * pk + 1][3]);
            #pragma unroll
            for (int nv = 0; nv < 8; nv++) {
                uint32_t tt[4];
                ldm4t(tt, Vb + (nv >> 2) * 8192 +
                          swz((pk * 16 + kb8 * 8 + li) * 128 + (nv & 3) * 32 + nb8 * 16));
                uint32_t b0[2] = {tt[0], tt[1]}, b1[2] = {tt[2], tt[3]};
                mma_f16(oacc[2 * nv],     af, b0);
                mma_f16(oacc[2 * nv + 1], af, b1);
            }
        }
        __syncthreads();
    }

    const float rc0 = frcp(l0), rc1 = frcp(l1);
    #pragma unroll
    for (int nt = 0; nt < 16; nt++) {
        const int col = nt * 8 + c * 2;
        st2(Op + (long)(w * 16 + g) * D_ + col,     oacc[nt][0] * rc0, oacc[nt][1] * rc0);
        st2(Op + (long)(w * 16 + g + 8) * D_ + col, oacc[nt][2] * rc1, oacc[nt][3] * rc1);
    }
}
#define FSMEM (4096 + 65536 + 65536 + 32768)

// ---------------------------------------------------------------------------
// FP16 GEMM 128x128x64 — used for QKV (EPI 5) and w1+gelu (EPI 2).
// ---------------------------------------------------------------------------
template<int EPI, typename TO>
__global__ void __launch_bounds__(128, 2)
gemm_k(const __half* __restrict__ A, const __half* __restrict__ Bm,
       const float* bias, TO* C, int M, int N, int K,
       TO* C2, TO* C3, const float* bias2, const float* bias3)
{
    extern __shared__ __half smh[];
    const uint32_t smu = smem_u32(smh);

    const int tid  = threadIdx.x;
    const int lane = tid & 31;
    const int wm   = (tid >> 5) & 1;
    const int wn   = tid >> 6;
    const int bm = blockIdx.y * 128;
    const int bn = blockIdx.x * 128;

    if (EPI == 5) {
        const int sel = bn >> 8;
        if (sel == 1) { C = C2; bias = bias2; }
        else if (sel == 2) { C = C3; bias = bias3; }
    }
    const int No = (EPI == 5) ? 256 : N;

    const __half* Ap = A  + (long)(bm + tid) * K;
    const __half* Bp = Bm + (long)(bn + tid) * K;
    uint32_t dsw[8];
    #pragma unroll
    for (int j = 0; j < 8; j++) dsw[j] = swz(tid * 128 + j * 16);

    uint32_t arow[4], brow[4];
    #pragma unroll
    for (int i = 0; i < 4; i++) {
        arow[i] = (wm * 64 + i * 16 + (lane & 15)) * 128 + (lane >> 4) * 16;
        brow[i] = (wn * 64 + i * 16 + (lane & 15)) * 128 + (lane >> 4) * 16;
    }
    const int g = lane >> 2;
    const int c = lane & 3;

    float acc[4][8][4];
    #pragma unroll
    for (int i = 0; i < 4; i++)
        #pragma unroll
        for (int j = 0; j < 8; j++)
            #pragma unroll
            for (int r = 0; r < 4; r++) acc[i][j][r] = 0.0f;

    const int nst = K >> 6;

    #pragma unroll
    for (int j = 0; j < 8; j++) {
        cp16(smu + dsw[j],         Ap + j * 8);
        cp16(smu + 16384 + dsw[j], Bp + j * 8);
    }
    cp_commit();

    int buf = 0;
    for (int s = 0; s < nst; s++) {
        if (s + 1 < nst) {
            const int kn = (s + 1) << 6;
            const uint32_t base = smu + (buf ^ 1) * 32768;
            #pragma unroll
            for (int j = 0; j < 8; j++) {
                cp16(base + dsw[j],         Ap + kn + j * 8);
                cp16(base + 16384 + dsw[j], Bp + kn + j * 8);
            }
            cp_commit();
            asm volatile("cp.async.wait_group 1;" ::: "memory");
        } else {
            asm volatile("cp.async.wait_group 0;" ::: "memory");
        }
        __syncthreads();

        const uint32_t Au = smu + buf * 32768;
        const uint32_t Bu = Au + 16384;
        #pragma unroll
        for (int kb = 0; kb < 4; kb++) {
            uint32_t af[4][4];
            uint32_t bf[8][2];
            #pragma unroll
            for (int ma = 0; ma < 4; ma++)
                ldm4(af[ma], Au + swz(arow[ma] + kb * 32));
            #pragma unroll
            for (int np = 0; np < 4; np++) {
                uint32_t t[4];
                ldm4(t, Bu + swz(brow[np] + kb * 32));
                bf[2*np][0]   = t[0];
                bf[2*np+1][0] = t[1];
                bf[2*np][1]   = t[2];
                bf[2*np+1][1] = t[3];
            }
            #pragma unroll
            for (int ma = 0; ma < 4; ma++)
                #pragma unroll
                for (int nb = 0; nb < 8; nb++)
                    mma_f16(acc[ma][nb], af[ma], bf[nb]);
        }
        __syncthreads();
        buf ^= 1;
    }

    #pragma unroll
    for (int nb = 0; nb < 8; nb++) {
        const int col  = bn + wn * 64 + nb * 8 + c * 2;
        const int colo = (EPI == 5) ? (col & 255) : col;
        float2 bv = *(const float2*)(bias + colo);

        #pragma unroll
        for (int ma = 0; ma < 4; ma++) {
            const int r0 = bm + wm * 64 + ma * 16 + g;
            const int r1 = r0 + 8;
            float d0 = acc[ma][nb][0] + bv.x, d1 = acc[ma][nb][1] + bv.y;
            float d2 = acc[ma][nb][2] + bv.x, d3 = acc[ma][nb][3] + bv.y;
            if (EPI == 2) {
                d0 = 0.5f * d0 * (1.0f + erff(d0 * 0.70710678118654752f));
                d1 = 0.5f * d1 * (1.0f + erff(d1 * 0.70710678118654752f));
                d2 = 0.5f * d2 * (1.0f + erff(d2 * 0.70710678118654752f));
                d3 = 0.5f * d3 * (1.0f + erff(d3 * 0.70710678118654752f));
            }
            st2(C + (long)r0 * No + colo, d0, d1);
            st2(C + (long)r1 * No + colo, d2, d3);
        }
    }
}
#define GSMEM 65536

// ---------------------------------------------------------------------------
// WIDE GEMM 128x256x64: 256 threads (8 warps: wm=w&1, wn=w>>1), warp 64x64.
// CTA computes full output rows -> LayerNorm fused in epilogue.
// MODE 6 (wo):  t = A@B + bias; x = h32 + LN_{g1,b1}(t); xo=x; C16=LN_{g2,b2}(x)
// MODE 7 (w2):  x = res32 + A@B + bias; xo=x; if g1: H=LN_{g1,b1}(x) -> h16,h32
// smem: 2 x (A 16KB + B 32KB) = 96KB; epilogue reduction reuses first 4KB.
// ---------------------------------------------------------------------------
template<int MODE>
__global__ void __launch_bounds__(256, 1)
gemmw_k(const __half* __restrict__ A, const __half* __restrict__ Bm,
        const float* __restrict__ bias, const float* __restrict__ res32,
        float* __restrict__ xo, __half* __restrict__ out16,
        float* __restrict__ out32,
        const float* __restrict__ g1, const float* __restrict__ b1v,
        const float* __restrict__ g2, const float* __restrict__ b2v)
{
    extern __shared__ __half smh[];
    const uint32_t smu = smem_u32(smh);
    float* red = (float*)smh;          // [128][4] sums + [128][4] sumsq = 4KB

    const int tid  = threadIdx.x;
    const int lane = tid & 31;
    const int w    = tid >> 5;
    const int wm   = w & 1;
    const int wn   = w >> 1;           // 0..3
    const int bm   = blockIdx.y * 128;

    // staging: A row = tid>>1 (4 chunks), B row = tid (8 chunks)
    const __half* Ap = A  + (long)(bm + (tid >> 1)) * D_ + (tid & 1) * 32;
    const __half* Bp = Bm + (long)tid * D_;
    uint32_t adsw[4], bdsw[8];
    #pragma unroll
    for (int j = 0; j < 4; j++)
        adsw[j] = swz((tid >> 1) * 128 + ((tid & 1) * 4 + j) * 16);
    #pragma unroll
    for (int j = 0; j < 8; j++) bdsw[j] = 16384 + swz(tid * 128 + j * 16);

    const int g = lane >> 2;
    const int c = lane & 3;

    float acc[4][8][4];
    #pragma unroll
    for (int i = 0; i < 4; i++)
        #pragma unroll
        for (int j = 0; j < 8; j++)
            #pragma unroll
            for (int r = 0; r < 4; r++) acc[i][j][r] = 0.0f;

    // prologue
    #pragma unroll
    for (int j = 0; j < 4; j++) cp16(smu + adsw[j], Ap + j * 8);
    #pragma unroll
    for (int j = 0; j < 8; j++) cp16(smu + bdsw[j], Bp + j * 8);
    cp_commit();

    int buf = 0;
    #pragma unroll
    for (int s = 0; s < 4; s++) {
        if (s < 3) {
            const int kn = (s + 1) << 6;
            const uint32_t base = smu + (buf ^ 1) * 49152;
            #pragma unroll
            for (int j = 0; j < 4; j++) cp16(base + adsw[j], Ap + kn + j * 8);
            #pragma unroll
            for (int j = 0; j < 8; j++) cp16(base + bdsw[j], Bp + kn + j * 8);
            cp_commit();
            asm volatile("cp.async.wait_group 1;" ::: "memory");
        } else {
            asm volatile("cp.async.wait_group 0;" ::: "memory");
        }
        __syncthreads();

        const uint32_t base = smu + buf * 49152;
        #pragma unroll
        for (int kb = 0; kb < 4; kb++) {
            uint32_t af[4][4];
            uint32_t bf[8][2];
            #pragma unroll
            for (int ma = 0; ma < 4; ma++)
                ldm4(af[ma], base +
                     swz((wm * 64 + ma * 16 + (lane & 15)) * 128 + kb * 32 + (lane >> 4) * 16));
            #pragma unroll
            for (int np = 0; np < 4; np++) {
                uint32_t t[4];
                ldm4(t, base + 16384 +
                        swz((wn * 64 + np * 16 + (lane & 15)) * 128 + kb * 32 + (lane >> 4) * 16));
                bf[2*np][0]   = t[0];
                bf[2*np+1][0] = t[1];
                bf[2*np][1]   = t[2];
                bf[2*np+1][1] = t[3];
            }
            #pragma unroll
            for (int ma = 0; ma < 4; ma++)
                #pragma unroll
                for (int nb = 0; nb < 8; nb++)
                    mma_f16(acc[ma][nb], af[ma], bf[nb]);
        }
        __syncthreads();
        buf ^= 1;
    }

    // ================= epilogue with fused LayerNorm(s) =================
    const int colb = wn * 64 + c * 2;      // + nb*8
    float2 biasv[8];
    #pragma unroll
    for (int nb = 0; nb < 8; nb++) biasv[nb] = *(const float2*)(bias + colb + nb * 8);

    #pragma unroll
    for (int ma = 0; ma < 4; ma++) {
        const long r0 = bm + wm * 64 + ma * 16 + g;
        #pragma unroll
        for (int nb = 0; nb < 8; nb++) {
            acc[ma][nb][0] += biasv[nb].x; acc[ma][nb][1] += biasv[nb].y;
            acc[ma][nb][2] += biasv[nb].x; acc[ma][nb][3] += biasv[nb].y;
            if (MODE == 7) {
                float2 ra = *(const float2*)(res32 + r0 * D_ + colb + nb * 8);
                float2 rb = *(const float2*)(res32 + (r0 + 8) * D_ + colb + nb * 8);
                acc[ma][nb][0] += ra.x; acc[ma][nb][1] += ra.y;
                acc[ma][nb][2] += rb.x; acc[ma][nb][3] += rb.y;
            }
        }
    }

    float mean0[4], inv0[4], mean1[4], inv1[4];
    auto reduce_rows = [&]() {
        #pragma unroll
        for (int ma = 0; ma < 4; ma++) {
            float s0 = 0, q0 = 0, s1 = 0, q1 = 0;
            #pragma unroll
            for (int nb = 0; nb < 8; nb++) {
                s0 += acc[ma][nb][0] + acc[ma][nb][1];
                q0 += acc[ma][nb][0] * acc[ma][nb][0] + acc[ma][nb][1] * acc[ma][nb][1];
                s1 += acc[ma][nb][2] + acc[ma][nb][3];
                q1 += acc[ma][nb][2] * acc[ma][nb][2] + acc[ma][nb][3] * acc[ma][nb][3];
            }
            s0 += __shfl_xor_sync(0xffffffffu, s0, 1); s0 += __shfl_xor_sync(0xffffffffu, s0, 2);
            q0 += __shfl_xor_sync(0xffffffffu, q0, 1); q0 += __shfl_xor_sync(0xffffffffu, q0, 2);
            s1 += __shfl_xor_sync(0xffffffffu, s1, 1); s1 += __shfl_xor_sync(0xffffffffu, s1, 2);
            q1 += __shfl_xor_sync(0xffffffffu, q1, 1); q1 += __shfl_xor_sync(0xffffffffu, q1, 2);
            if (c == 0) {
                const int r = wm * 64 + ma * 16 + g;
                red[r * 4 + wn]       = s0;  red[512 + r * 4 + wn]       = q0;
                red[(r + 8) * 4 + wn] = s1;  red[512 + (r + 8) * 4 + wn] = q1;
            }
        }
        __syncthreads();
        #pragma unroll
        for (int ma = 0; ma < 4; ma++) {
            const int r = wm * 64 + ma * 16 + g;
            float s0 = red[r*4] + red[r*4+1] + red[r*4+2] + red[r*4+3];
            float q0 = red[512+r*4] + red[512+r*4+1] + red[512+r*4+2] + red[512+r*4+3];
            float s1 = red[(r+8)*4] + red[(r+8)*4+1] + red[(r+8)*4+2] + red[(r+8)*4+3];
            float q1 = red[512+(r+8)*4] + red[512+(r+8)*4+1] + red[512+(r+8)*4+2] + red[512+(r+8)*4+3];
            mean0[ma] = s0 * (1.0f / 256.0f);
            inv0[ma]  = rsqrtf(q0 * (1.0f / 256.0f) - mean0[ma] * mean0[ma] + 1e-5f);
            mean1[ma] = s1 * (1.0f / 256.0f);
            inv1[ma]  = rsqrtf(q1 * (1.0f / 256.0f) - mean1[ma] * mean1[ma] + 1e-5f);
        }
        __syncthreads();
    };

    __syncthreads();
    if (MODE == 7 && g1 == nullptr) {
        #pragma unroll
        for (int ma = 0; ma < 4; ma++) {
            const long r0 = bm + wm * 64 + ma * 16 + g;
            #pragma unroll
            for (int nb = 0; nb < 8; nb++) {
                st2(xo + r0 * D_ + colb + nb * 8,       acc[ma][nb][0], acc[ma][nb][1]);
                st2(xo + (r0 + 8) * D_ + colb + nb * 8, acc[ma][nb][2], acc[ma][nb][3]);
            }
        }
        return;
    }

    reduce_rows();   // stats of t (MODE 6) or x (MODE 7)

    float2 g1v[8], b1vv[8];
    #pragma unroll
    for (int nb = 0; nb < 8; nb++) {
        g1v[nb]  = *(const float2*)(g1 + colb + nb * 8);
        b1vv[nb] = *(const float2*)(b1v + colb + nb * 8);
    }

    if (MODE == 7) {
        #pragma unroll
        for (int ma = 0; ma < 4; ma++) {
            const long r0 = bm + wm * 64 + ma * 16 + g;
            #pragma unroll
            for (int nb = 0; nb < 8; nb++) {
                const int cc = colb + nb * 8;
                float x0 = acc[ma][nb][0], x1 = acc[ma][nb][1];
                float x2 = acc[ma][nb][2], x3 = acc[ma][nb][3];
                st2(xo + r0 * D_ + cc, x0, x1);
                st2(xo + (r0 + 8) * D_ + cc, x2, x3);
                float h0 = (x0 - mean0[ma]) * inv0[ma] * g1v[nb].x + b1vv[nb].x;
                float h1 = (x1 - mean0[ma]) * inv0[ma] * g1v[nb].y + b1vv[nb].y;
                float h2 = (x2 - mean1[ma]) * inv1[ma] * g1v[nb].x + b1vv[nb].x;
                float h3 = (x3 - mean1[ma]) * inv1[ma] * g1v[nb].y + b1vv[nb].y;
                st2(out32 + r0 * D_ + cc, h0, h1);
                st2(out32 + (r0 + 8) * D_ + cc, h2, h3);
                st2(out16 + r0 * D_ + cc, h0, h1);
                st2(out16 + (r0 + 8) * D_ + cc, h2, h3);
            }
        }
        return;
    }

    // MODE 6: x = h32 + LN(t); second LN for C16
    #pragma unroll
    for (int ma = 0; ma < 4; ma++) {
        const long r0 = bm + wm * 64 + ma * 16 + g;
        #pragma unroll
        for (int nb = 0; nb < 8; nb++) {
            const int cc = colb + nb * 8;
            float2 ha = *(const float2*)(res32 + r0 * D_ + cc);
            float2 hb = *(const float2*)(res32 + (r0 + 8) * D_ + cc);
            acc[ma][nb][0] = ha.x + (acc[ma][nb][0] - mean0[ma]) * inv0[ma] * g1v[nb].x + b1vv[nb].x;
            acc[ma][nb][1] = ha.y + (acc[ma][nb][1] - mean0[ma]) * inv0[ma] * g1v[nb].y + b1vv[nb].y;
            acc[ma][nb][2] = hb.x + (acc[ma][nb][2] - mean1[ma]) * inv1[ma] * g1v[nb].x + b1vv[nb].x;
            acc[ma][nb][3] = hb.y + (acc[ma][nb][3] - mean1[ma]) * inv1[ma] * g1v[nb].y + b1vv[nb].y;
        }
    }
    reduce_rows();   // stats of x

    #pragma unroll
    for (int nb = 0; nb < 8; nb++) {
        g1v[nb]  = *(const float2*)(g2 + colb + nb * 8);
        b1vv[nb] = *(const float2*)(b2v + colb + nb * 8);
    }
    #pragma unroll
    for (int ma = 0; ma < 4; ma++) {
        const long r0 = bm + wm * 64 + ma * 16 + g;
        #pragma unroll
        for (int nb = 0; nb < 8; nb++) {
            const int cc = colb + nb * 8;
            float x0 = acc[ma][nb][0], x1 = acc[ma][nb][1];
            float x2 = acc[ma][nb][2], x3 = acc[ma][nb][3];
            st2(xo + r0 * D_ + cc, x0, x1);
            st2(xo + (r0 + 8) * D_ + cc, x2, x3);
            float c0 = (x0 - mean0[ma]) * inv0[ma] * g1v[nb].x + b1vv[nb].x;
            float c1 = (x1 - mean0[ma]) * inv0[ma] * g1v[nb].y + b1vv[nb].y;
            float c2 = (x2 - mean1[ma]) * inv1[ma] * g1v[nb].x + b1vv[nb].x;
            float c3 = (x3 - mean1[ma]) * inv1[ma] * g1v[nb].y + b1vv[nb].y;
            st2(out16 + r0 * D_ + cc, c0, c1);
            st2(out16 + (r0 + 8) * D_ + cc, c2, c3);
        }
    }
}
#define WSMEM 98304

// ---------------------------------------------------------------------------
// Launcher
// ---------------------------------------------------------------------------
extern "C" void kernel_launch(void* const* d_in, const int* in_sizes, int n_in,
                              void* d_out, int out_size)
{
    const float* x    = (const float*)d_in[0];
    const int*   mask = (const int*)  d_in[1];
    const float* btab = (const float*)d_in[2];
    const float* ln_g = (const float*)d_in[3];
    const float* ln_b = (const float*)d_in[4];
    const float* wq   = (const float*)d_in[5];
    const float* bq   = (const float*)d_in[6];
    const float* wk   = (const float*)d_in[7];
    const float* bk   = (const float*)d_in[8];
    const float* wv   = (const float*)d_in[9];
    const float* bv   = (const float*)d_in[10];
    const float* wo   = (const float*)d_in[11];
    const float* bo   = (const float*)d_in[12];
    const float* cmg  = (const float*)d_in[13];
    const float* cmb  = (const float*)d_in[14];
    const float* w1   = (const float*)d_in[15];
    const float* b1   = (const float*)d_in[16];
    const float* w2   = (const float*)d_in[17];
    const float* b2   = (const float*)d_in[18];
    float* xo = (float*)d_out;

    __half *H16, *Q16, *K16, *V16, *O16, *C16, *F16, *WT, *WQKV;
    float *H32;
    cudaGetSymbolAddress((void**)&H16,  g_H16);
    cudaGetSymbolAddress((void**)&Q16,  g_Q16);
    cudaGetSymbolAddress((void**)&K16,  g_K16);
    cudaGetSymbolAddress((void**)&V16,  g_V16);
    cudaGetSymbolAddress((void**)&O16,  g_O16);
    cudaGetSymbolAddress((void**)&C16,  g_C16);
    cudaGetSymbolAddress((void**)&F16,  g_F16);
    cudaGetSymbolAddress((void**)&WT,   g_WT16);
    cudaGetSymbolAddress((void**)&WQKV, g_WQKV);
    cudaGetSymbolAddress((void**)&H32,  g_H32);

    cudaFuncSetAttribute(gemm_k<5, __half>, cudaFuncAttributeMaxDynamicSharedMemorySize, GSMEM);
    cudaFuncSetAttribute(gemm_k<2, __half>, cudaFuncAttributeMaxDynamicSharedMemorySize, GSMEM);
    cudaFuncSetAttribute(gemmw_k<6>, cudaFuncAttributeMaxDynamicSharedMemorySize, WSMEM);
    cudaFuncSetAttribute(gemmw_k<7>, cudaFuncAttributeMaxDynamicSharedMemorySize, WSMEM);
    cudaFuncSetAttribute(flash_k, cudaFuncAttributeMaxDynamicSharedMemorySize, FSMEM);

    // one-time weight transposes (fp32 -> fp16, transposed)
    const dim3 trWg(8, 8, 3), trB(32, 8);
    trW_k<<<trWg, trB>>>(wq, WQKV + 0L * WSZ, D_, D_, 3L * WSZ);
    trW_k<<<trWg, trB>>>(wk, WQKV + 1L * WSZ, D_, D_, 3L * WSZ);
    trW_k<<<trWg, trB>>>(wv, WQKV + 2L * WSZ, D_, D_, 3L * WSZ);
    trW_k<<<trWg, trB>>>(wo, WT + 0L * 3 * WSZ, D_, D_, WSZ);
    trW_k<<<trWg, trB>>>(w1, WT + 1L * 3 * WSZ, D_, D_, WSZ);
    trW_k<<<trWg, trB>>>(w2, WT + 2L * 3 * WSZ, D_, D_, WSZ);

    const dim3 gQKV(6, ROWS / 128, 1);
    const dim3 gProj(D_ / 128, ROWS / 128, 1);
    const dim3 gWide(1, ROWS / 128, 1);          // 256 CTAs (M=128 tiles)
    const dim3 gFlash(2, S_ / 128, B_);
    const int  rowBlocks = ROWS / 8;

    // layer-0 input LN
    ln_k<<<rowBlocks, 256>>>(x, ln_g, ln_b, H16, H32, ROWS);

    for (int j = 0; j < 3; j++) {
        const float* gj = ln_g + j * D_;
        const float* bj = ln_b + j * D_;
        const __half* wqkvT = WQKV + (long)j * 3 * WSZ;
        const __half* woT   = WT + (0L * 3 + j) * WSZ;
        const __half* w1T   = WT + (1L * 3 + j) * WSZ;
        const __half* w2T   = WT + (2L * 3 + j) * WSZ;

        // q,k,v = h @ {wq,wk,wv} + bias (fused, routed)
        gemm_k<5, __half><<<gQKV, 128, GSMEM>>>(H16, wqkvT, bq + j * D_, Q16,
                                                ROWS, 768, D_,
                                                K16, V16, bk + j * D_, bv + j * D_);

        // o = attention(q, k, v)
        flash_k<<<gFlash, 256, FSMEM>>>(Q16, K16, V16, mask, btab, O16);

        // x = h + LN(o@wo+bo); c = LN_cm(x)   (fused wide GEMM)
        gemmw_k<6><<<gWide, 256, WSMEM>>>(O16, woT, bo + j * D_, H32,
                                          xo, C16, nullptr,
                                          gj, bj, cmg + j * D_, cmb + j * D_);

        // f = gelu(c @ w1 + b1)
        gemm_k<2, __half><<<gProj, 128, GSMEM>>>(C16, w1T, b1 + j * D_, F16,
                                                 ROWS, D_, D_,
                                                 (__half*)nullptr, (__half*)nullptr, nullptr, nullptr);

        // x = x + f@w2 + b2 ; h_next = LN(x) (layers 0,1)
        const bool last = (j == 2);
        gemmw_k<7><<<gWide, 256, WSMEM>>>(F16, w2T, b2 + j * D_, xo,
                                          xo, last ? nullptr : H16,
                                          last ? nullptr : H32,
                                          last ? nullptr : ln_g + (j + 1) * D_,
                                          last ? nullptr : ln_b + (j + 1) * D_,
                                          nullptr, nullptr);
    }
}

// round 15
// speedup vs baseline: 1.2602x; 1.0749x over previous
#include <cuda_runtime.h>
#include <cuda_fp16.h>
#include <math.h>
#include <stdint.h>

// Problem dims (fixed)
#define B_   64
#define S_   512
#define D_   256
#define ROWS (B_ * S_)          // 32768
#define WSZ  (D_ * D_)          // 65536 per-layer weight size
#define L2E  1.4426950408889634f

// ---------------------------------------------------------------------------
// Scratch (device globals; no allocation allowed)
// ---------------------------------------------------------------------------
__device__ __half g_H16[ROWS * D_];
__device__ __half g_Q16[ROWS * D_];
__device__ __half g_K16[ROWS * D_];
__device__ __half g_V16[ROWS * D_];
__device__ __half g_O16[ROWS * D_];
__device__ __half g_C16[ROWS * D_];
__device__ __half g_F16[ROWS * D_];
__device__ __half g_WT16[3 * 3 * WSZ];        // wo,w1,w2 transposed fp16
__device__ __half g_WQKV[3 * 3 * WSZ];        // per-layer [768][256] fp16
__device__ float  g_H32[ROWS * D_];           // LN(x) fp32 (residual use)

// ---------------------------------------------------------------------------
// helpers
// ---------------------------------------------------------------------------
__device__ __forceinline__ uint32_t smem_u32(const void* p) {
    uint32_t a;
    asm("{ .reg .u64 t; cvta.to.shared.u64 t, %1; cvt.u32.u64 %0, t; }"
        : "=r"(a) : "l"(p));
    return a;
}
__device__ __forceinline__ uint32_t swz(uint32_t byte) {   // SW128
    return byte ^ ((byte >> 3) & 0x70);
}
__device__ __forceinline__ void cp16(uint32_t dst, const void* src) {
    asm volatile("cp.async.cg.shared.global [%0], [%1], 16;"
                 :: "r"(dst), "l"(src) : "memory");
}
__device__ __forceinline__ void cp_commit() {
    asm volatile("cp.async.commit_group;" ::: "memory");
}
__device__ __forceinline__ void ldm4(uint32_t* r, uint32_t a) {
    asm volatile("ldmatrix.sync.aligned.m8n8.x4.shared.b16 {%0,%1,%2,%3}, [%4];"
                 : "=r"(r[0]), "=r"(r[1]), "=r"(r[2]), "=r"(r[3]) : "r"(a));
}
__device__ __forceinline__ void ldm4t(uint32_t* r, uint32_t a) {
    asm volatile("ldmatrix.sync.aligned.m8n8.x4.trans.shared.b16 {%0,%1,%2,%3}, [%4];"
                 : "=r"(r[0]), "=r"(r[1]), "=r"(r[2]), "=r"(r[3]) : "r"(a));
}
__device__ __forceinline__ void mma_f16(float* d, const uint32_t* a, const uint32_t* b) {
    asm volatile(
        "mma.sync.aligned.m16n8k16.row.col.f32.f16.f16.f32 "
        "{%0,%1,%2,%3}, {%4,%5,%6,%7}, {%8,%9}, {%0,%1,%2,%3};"
        : "+f"(d[0]), "+f"(d[1]), "+f"(d[2]), "+f"(d[3])
        : "r"(a[0]), "r"(a[1]), "r"(a[2]), "r"(a[3]), "r"(b[0]), "r"(b[1]));
}
__device__ __forceinline__ float ex2(float x) {    // single MUFU.EX2
    float r;
    asm("ex2.approx.f32 %0, %1;" : "=f"(r) : "f"(x));
    return r;
}
__device__ __forceinline__ float frcp(float x) {   // single MUFU.RCP
    float r;
    asm("rcp.approx.f32 %0, %1;" : "=f"(r) : "f"(x));
    return r;
}
__device__ __forceinline__ void st2(float* p, float a, float b) {
    *(float2*)p = make_float2(a, b);
}
__device__ __forceinline__ void st2(__half* p, float a, float b) {
    *(__half2*)p = __floats2half2_rn(a, b);
}

// ---------------------------------------------------------------------------
// Weight transpose: float in -> half out, out[c][r] = in[r][c]; z-stride param
// ---------------------------------------------------------------------------
__global__ void trW_k(const float* __restrict__ in, __half* __restrict__ out,
                      int rows, int cols, long ostride)
{
    __shared__ float t[32][33];
    in  += blockIdx.z * (long)rows * cols;
    out += blockIdx.z * ostride;
    const int r0 = blockIdx.y * 32, c0 = blockIdx.x * 32;
    const int tx = threadIdx.x, ty = threadIdx.y;
    #pragma unroll
    for (int i = 0; i < 32; i += 8)
        t[ty + i][tx] = in[(long)(r0 + ty + i) * cols + c0 + tx];
    __syncthreads();
    #pragma unroll
    for (int i = 0; i < 32; i += 8)
        out[(long)(c0 + ty + i) * rows + r0 + tx] = __float2half_rn(t[tx][ty + i]);
}

// ---------------------------------------------------------------------------
// LayerNorm (used once, layer 0 input): one warp per row -> H16 + H32
// ---------------------------------------------------------------------------
__global__ void ln_k(const float* __restrict__ in,
                     const float* __restrict__ g, const float* __restrict__ b,
                     __half* __restrict__ out16, float* __restrict__ out32, int rows)
{
    int warp = (blockIdx.x * blockDim.x + threadIdx.x) >> 5;
    int lane = threadIdx.x & 31;
    if (warp >= rows) return;

    const float4* x4 = (const float4*)(in + (long)warp * D_);
    float4 v0 = x4[lane];
    float4 v1 = x4[lane + 32];

    float s = v0.x + v0.y + v0.z + v0.w + v1.x + v1.y + v1.z + v1.w;
    #pragma unroll
    for (int o = 16; o; o >>= 1) s += __shfl_xor_sync(0xffffffffu, s, o);
    float mean = s * (1.0f / 256.0f);

    float d0x = v0.x - mean, d0y = v0.y - mean, d0z = v0.z - mean, d0w = v0.w - mean;
    float d1x = v1.x - mean, d1y = v1.y - mean, d1z = v1.z - mean, d1w = v1.w - mean;
    float q = d0x*d0x + d0y*d0y + d0z*d0z + d0w*d0w
            + d1x*d1x + d1y*d1y + d1z*d1z + d1w*d1w;
    #pragma unroll
    for (int o = 16; o; o >>= 1) q += __shfl_xor_sync(0xffffffffu, q, o);
    float inv = rsqrtf(q * (1.0f / 256.0f) + 1e-5f);

    const float4* g4 = (const float4*)g;
    const float4* b4 = (const float4*)b;
    float4 gv0 = g4[lane], gv1 = g4[lane + 32];
    float4 bv0 = b4[lane], bv1 = b4[lane + 32];

    float4 o0, o1;
    o0.x = d0x * inv * gv0.x + bv0.x;  o0.y = d0y * inv * gv0.y + bv0.y;
    o0.z = d0z * inv * gv0.z + bv0.z;  o0.w = d0w * inv * gv0.w + bv0.w;
    o1.x = d1x * inv * gv1.x + bv1.x;  o1.y = d1y * inv * gv1.y + bv1.y;
    o1.z = d1z * inv * gv1.z + bv1.z;  o1.w = d1w * inv * gv1.w + bv1.w;

    float4* out4 = (float4*)(out32 + (long)warp * D_);
    out4[lane]      = o0;
    out4[lane + 32] = o1;
    __half2* oh = (__half2*)(out16 + (long)warp * D_);
    oh[lane * 2]            = __floats2half2_rn(o0.x, o0.y);
    oh[lane * 2 + 1]        = __floats2half2_rn(o0.z, o0.w);
    oh[(lane + 32) * 2]     = __floats2half2_rn(o1.x, o1.y);
    oh[(lane + 32) * 2 + 1] = __floats2half2_rn(o1.z, o1.w);
}

// ---------------------------------------------------------------------------
// Fused flash attention v2 — no QK^T duplication.
// CTA = 64 q-rows x full 256 D. 8 warps: wr = w&3 (16-row group),
// wc = w>>2 (32-key half for S; 128-col half for O).
// Per 64-key tile: warp computes S for its 16 rows x 32 keys, exponentiates,
// stores P (fp16) to an 8KB smem panel, then all warps do PV from P + V.
// Row-sum l kept as per-thread linear partials; reduced once at the end.
// smem: btab [0,4K) | P [4K,12K) | lsum [12K,12.5K) | KV0 @13312 (K32K+V32K)
//       | KV1 @78848  => 144384 B total (1 CTA/SM, same as before).
// ---------------------------------------------------------------------------
__global__ void __launch_bounds__(256)
flash_k(const __half* __restrict__ Qg, const __half* __restrict__ Kg,
        const __half* __restrict__ Vg, const int* __restrict__ mask,
        const float* __restrict__ btab, __half* __restrict__ Og)
{
    extern __shared__ char sm[];
    const uint32_t smu = smem_u32(sm);
    float* btab_s = (float*)sm;
    float* lsum   = (float*)(sm + 12288);
    const uint32_t Pu  = smu + 4096;
    const uint32_t KV0 = smu + 13312;
    const uint32_t KV1 = KV0 + 65536;

    const int tid = threadIdx.x, lane = tid & 31, w = tid >> 5;
    const int wr = w & 3, wc = w >> 2;
    const int r0 = blockIdx.x * 64, bz = blockIdx.z;

    const __half* Qp = Qg + ((long)bz * S_ + r0) * D_;
    const __half* Kp = Kg + (long)bz * S_ * D_;
    const __half* Vp = Vg + (long)bz * S_ * D_;
    __half* Op = Og + ((long)bz * S_ + r0) * D_;
    const int* mk = mask + bz * S_;

    ((float4*)btab_s)[tid] = ((const float4*)btab)[tid];

    const int sr = tid >> 2, sch = tid & 3;

    // ---- stage Q (32KB, 4 panels [64][64]) through KV0, load fragments ----
    {
        const __half* src = Qp + (long)sr * D_;
        #pragma unroll
        for (int p = 0; p < 4; p++) {
            cp16(KV0 + p * 8192 + swz(sr * 128 + sch * 16),       src + p * 64 + sch * 8);
            cp16(KV0 + p * 8192 + swz(sr * 128 + (sch + 4) * 16), src + p * 64 + (sch + 4) * 8);
        }
        cp_commit();
    }
    asm volatile("cp.async.wait_group 0;" ::: "memory");
    __syncthreads();

    uint32_t qf[16][4];
    {
        const int qrow = wr * 16 + (lane & 15);
        #pragma unroll
        for (int kt = 0; kt < 16; kt++)
            ldm4(qf[kt], KV0 + (kt >> 2) * 8192 +
                         swz(qrow * 128 + (kt & 3) * 32 + (lane >> 4) * 16));
    }
    __syncthreads();   // Q reads done before KV pipeline overwrites KV0

    auto stageKV = [&](int t, int bf) {
        const __half* ks = Kp + (long)(t * 64 + sr) * D_;
        const __half* vs = Vp + (long)(t * 64 + sr) * D_;
        const uint32_t kd = bf ? KV1 : KV0;
        const uint32_t vd = kd + 32768;
        #pragma unroll
        for (int p = 0; p < 4; p++) {
            cp16(kd + p * 8192 + swz(sr * 128 + sch * 16),       ks + p * 64 + sch * 8);
            cp16(kd + p * 8192 + swz(sr * 128 + (sch + 4) * 16), ks + p * 64 + (sch + 4) * 8);
            cp16(vd + p * 8192 + swz(sr * 128 + sch * 16),       vs + p * 64 + sch * 8);
            cp16(vd + p * 8192 + swz(sr * 128 + (sch + 4) * 16), vs + p * 64 + (sch + 4) * 8);
        }
    };
    stageKV(0, 0); cp_commit();

    const int g = lane >> 2, c = lane & 3;
    const int rowg = r0 + wr * 16 + g;
    const int kb8 = (lane >> 3) & 1, nb8 = lane >> 4, li = lane & 7;

    float oacc[16][4];                 // 16 rows x (wc*128 + nt*8) cols
    #pragma unroll
    for (int i = 0; i < 16; i++)
        #pragma unroll
        for (int r = 0; r < 4; r++) oacc[i][r] = 0.0f;
    float l0 = 0.0f, l1 = 0.0f;        // per-thread linear partials

    for (int t = 0; t < 8; t++) {
        const int bf = t & 1;
        if (t < 7) {
            stageKV(t + 1, bf ^ 1);
            cp_commit();
            asm volatile("cp.async.wait_group 1;" ::: "memory");
        } else {
            asm volatile("cp.async.wait_group 0;" ::: "memory");
        }
        __syncthreads();

        // ---- S = Q K^T : 16 rows x 32 keys (warp's key half) ----
        float sacc[4][4];
        #pragma unroll
        for (int i = 0; i < 4; i++)
            #pragma unroll
            for (int r = 0; r < 4; r++) sacc[i][r] = 0.0f;
        const uint32_t Kb = bf ? KV1 : KV0;
        #pragma unroll
        for (int kt = 0; kt < 16; kt++) {
            #pragma unroll
            for (int np = 0; np < 2; np++) {
                uint32_t tt[4];
                ldm4(tt, Kb + (kt >> 2) * 8192 +
                         swz((wc * 32 + np * 16 + (lane & 15)) * 128 +
                             (kt & 3) * 32 + (lane >> 4) * 16));
                uint32_t b0[2] = {tt[0], tt[2]}, b1[2] = {tt[1], tt[3]};
                mma_f16(sacc[2 * np],     qf[kt], b0);
                mma_f16(sacc[2 * np + 1], qf[kt], b1);
            }
        }

        // ---- p = exp(s + bias), masked -> 0 ; accumulate partials ----
        #pragma unroll
        for (int nt = 0; nt < 4; nt++) {
            const int n = t * 64 + wc * 32 + nt * 8 + c * 2;
            const int mk0 = mk[n], mk1 = mk[n + 1];
            int rel, bk;
            rel = n - rowg;           bk = rel < 0 ? 511 - rel : rel;
            float s00 = fmaf(sacc[nt][0], 0.0625f, btab_s[bk]);
            rel = n + 1 - rowg;       bk = rel < 0 ? 511 - rel : rel;
            float s01 = fmaf(sacc[nt][1], 0.0625f, btab_s[bk]);
            rel = n - (rowg + 8);     bk = rel < 0 ? 511 - rel : rel;
            float s10 = fmaf(sacc[nt][2], 0.0625f, btab_s[bk]);
            rel = n + 1 - (rowg + 8); bk = rel < 0 ? 511 - rel : rel;
            float s11 = fmaf(sacc[nt][3], 0.0625f, btab_s[bk]);
            float p00 = mk0 ? ex2(s00 * L2E) : 0.0f;
            float p01 = mk1 ? ex2(s01 * L2E) : 0.0f;
            float p10 = mk0 ? ex2(s10 * L2E) : 0.0f;
            float p11 = mk1 ? ex2(s11 * L2E) : 0.0f;
            l0 += p00 + p01;
            l1 += p10 + p11;
            sacc[nt][0] = p00; sacc[nt][1] = p01; sacc[nt][2] = p10; sacc[nt][3] = p11;
        }

        // ---- store P (fp16) to smem panel [64 rows][64 keys] ----
        #pragma unroll
        for (int nt = 0; nt < 4; nt++) {
            const int cc = wc * 32 + nt * 8 + c * 2;
            *(__half2*)(sm + 4096 + swz((wr * 16 + g) * 128 + cc * 2)) =
                __floats2half2_rn(sacc[nt][0], sacc[nt][1]);
            *(__half2*)(sm + 4096 + swz((wr * 16 + g + 8) * 128 + cc * 2)) =
                __floats2half2_rn(sacc[nt][2], sacc[nt][3]);
        }
        __syncthreads();   // P visible; K reads complete

        // ---- O += P @ V : 16 rows x 128 cols (warp's col half) ----
        const uint32_t Vb = (bf ? KV1 : KV0) + 32768;
        #pragma unroll
        for (int pk = 0; pk < 4; pk++) {
            uint32_t af[4];
            ldm4(af, Pu + swz((wr * 16 + (lane & 15)) * 128 + pk * 32 + (lane >> 4) * 16));
            #pragma unroll
            for (int nv = 0; nv < 8; nv++) {
                uint32_t tt[4];
                const int vp = wc * 2 + (nv >> 2);
                ldm4t(tt, Vb + vp * 8192 +
                          swz((pk * 16 + kb8 * 8 + li) * 128 + (nv & 3) * 32 + nb8 * 16));
                uint32_t b0[2] = {tt[0], tt[1]}, b1[2] = {tt[2], tt[3]};
                mma_f16(oacc[2 * nv],     af, b0);
                mma_f16(oacc[2 * nv + 1], af, b1);
            }
        }
        __syncthreads();   // V & P reads done before next tile writes
    }

    // ---- final l reduction: across c (shfl) then across wc (smem) ----
    l0 += __shfl_xor_sync(0xffffffffu, l0, 1);
    l0 += __shfl_xor_sync(0xffffffffu, l0, 2);
    l1 += __shfl_xor_sync(0xffffffffu, l1, 1);
    l1 += __shfl_xor_sync(0xffffffffu, l1, 2);
    if (c == 0) {
        lsum[(wr * 16 + g) * 2 + wc]     = l0;
        lsum[(wr * 16 + g + 8) * 2 + wc] = l1;
    }
    __syncthreads();
    const float rc0 = frcp(lsum[(wr * 16 + g) * 2]     + lsum[(wr * 16 + g) * 2 + 1]);
    const float rc1 = frcp(lsum[(wr * 16 + g + 8) * 2] + lsum[(wr * 16 + g + 8) * 2 + 1]);

    #pragma unroll
    for (int nt = 0; nt < 16; nt++) {
        const int col = wc * 128 + nt * 8 + c * 2;
        st2(Op + (long)(wr * 16 + g) * D_ + col,     oacc[nt][0] * rc0, oacc[nt][1] * rc0);
        st2(Op + (long)(wr * 16 + g + 8) * D_ + col, oacc[nt][2] * rc1, oacc[nt][3] * rc1);
    }
}
#define FSMEM 144384

// ---------------------------------------------------------------------------
// FP16 GEMM 128x128x64 — used for QKV (EPI 5) and w1+gelu (EPI 2).
// ---------------------------------------------------------------------------
template<int EPI, typename TO>
__global__ void __launch_bounds__(128, 2)
gemm_k(const __half* __restrict__ A, const __half* __restrict__ Bm,
       const float* bias, TO* C, int M, int N, int K,
       TO* C2, TO* C3, const float* bias2, const float* bias3)
{
    extern __shared__ __half smh[];
    const uint32_t smu = smem_u32(smh);

    const int tid  = threadIdx.x;
    const int lane = tid & 31;
    const int wm   = (tid >> 5) & 1;
    const int wn   = tid >> 6;
    const int bm = blockIdx.y * 128;
    const int bn = blockIdx.x * 128;

    if (EPI == 5) {
        const int sel = bn >> 8;
        if (sel == 1) { C = C2; bias = bias2; }
        else if (sel == 2) { C = C3; bias = bias3; }
    }
    const int No = (EPI == 5) ? 256 : N;

    const __half* Ap = A  + (long)(bm + tid) * K;
    const __half* Bp = Bm + (long)(bn + tid) * K;
    uint32_t dsw[8];
    #pragma unroll
    for (int j = 0; j < 8; j++) dsw[j] = swz(tid * 128 + j * 16);

    uint32_t arow[4], brow[4];
    #pragma unroll
    for (int i = 0; i < 4; i++) {
        arow[i] = (wm * 64 + i * 16 + (lane & 15)) * 128 + (lane >> 4) * 16;
        brow[i] = (wn * 64 + i * 16 + (lane & 15)) * 128 + (lane >> 4) * 16;
    }
    const int g = lane >> 2;
    const int c = lane & 3;

    float acc[4][8][4];
    #pragma unroll
    for (int i = 0; i < 4; i++)
        #pragma unroll
        for (int j = 0; j < 8; j++)
            #pragma unroll
            for (int r = 0; r < 4; r++) acc[i][j][r] = 0.0f;

    const int nst = K >> 6;

    #pragma unroll
    for (int j = 0; j < 8; j++) {
        cp16(smu + dsw[j],         Ap + j * 8);
        cp16(smu + 16384 + dsw[j], Bp + j * 8);
    }
    cp_commit();

    int buf = 0;
    for (int s = 0; s < nst; s++) {
        if (s + 1 < nst) {
            const int kn = (s + 1) << 6;
            const uint32_t base = smu + (buf ^ 1) * 32768;
            #pragma unroll
            for (int j = 0; j < 8; j++) {
                cp16(base + dsw[j],         Ap + kn + j * 8);
                cp16(base + 16384 + dsw[j], Bp + kn + j * 8);
            }
            cp_commit();
            asm volatile("cp.async.wait_group 1;" ::: "memory");
        } else {
            asm volatile("cp.async.wait_group 0;" ::: "memory");
        }
        __syncthreads();

        const uint32_t Au = smu + buf * 32768;
        const uint32_t Bu = Au + 16384;
        #pragma unroll
        for (int kb = 0; kb < 4; kb++) {
            uint32_t af[4][4];
            uint32_t bf[8][2];
            #pragma unroll
            for (int ma = 0; ma < 4; ma++)
                ldm4(af[ma], Au + swz(arow[ma] + kb * 32));
            #pragma unroll
            for (int np = 0; np < 4; np++) {
                uint32_t t[4];
                ldm4(t, Bu + swz(brow[np] + kb * 32));
                bf[2*np][0]   = t[0];
                bf[2*np+1][0] = t[1];
                bf[2*np][1]   = t[2];
                bf[2*np+1][1] = t[3];
            }
            #pragma unroll
            for (int ma = 0; ma < 4; ma++)
                #pragma unroll
                for (int nb = 0; nb < 8; nb++)
                    mma_f16(acc[ma][nb], af[ma], bf[nb]);
        }
        __syncthreads();
        buf ^= 1;
    }

    #pragma unroll
    for (int nb = 0; nb < 8; nb++) {
        const int col  = bn + wn * 64 + nb * 8 + c * 2;
        const int colo = (EPI == 5) ? (col & 255) : col;
        float2 bv = *(const float2*)(bias + colo);

        #pragma unroll
        for (int ma = 0; ma < 4; ma++) {
            const int r0 = bm + wm * 64 + ma * 16 + g;
            const int r1 = r0 + 8;
            float d0 = acc[ma][nb][0] + bv.x, d1 = acc[ma][nb][1] + bv.y;
            float d2 = acc[ma][nb][2] + bv.x, d3 = acc[ma][nb][3] + bv.y;
            if (EPI == 2) {
                d0 = 0.5f * d0 * (1.0f + erff(d0 * 0.70710678118654752f));
                d1 = 0.5f * d1 * (1.0f + erff(d1 * 0.70710678118654752f));
                d2 = 0.5f * d2 * (1.0f + erff(d2 * 0.70710678118654752f));
                d3 = 0.5f * d3 * (1.0f + erff(d3 * 0.70710678118654752f));
            }
            st2(C + (long)r0 * No + colo, d0, d1);
            st2(C + (long)r1 * No + colo, d2, d3);
        }
    }
}
#define GSMEM 65536

// ---------------------------------------------------------------------------
// WIDE GEMM 128x256x64: 256 threads (8 warps: wm=w&1, wn=w>>1), warp 64x64.
// CTA computes full output rows -> LayerNorm fused in epilogue.
// MODE 6 (wo):  t = A@B + bias; x = h32 + LN_{g1,b1}(t); xo=x; C16=LN_{g2,b2}(x)
// MODE 7 (w2):  x = res32 + A@B + bias; xo=x; if g1: H=LN_{g1,b1}(x) -> h16,h32
// smem: 2 x (A 16KB + B 32KB) = 96KB; epilogue reduction reuses first 4KB.
// ---------------------------------------------------------------------------
template<int MODE>
__global__ void __launch_bounds__(256, 1)
gemmw_k(const __half* __restrict__ A, const __half* __restrict__ Bm,
        const float* __restrict__ bias, const float* __restrict__ res32,
        float* __restrict__ xo, __half* __restrict__ out16,
        float* __restrict__ out32,
        const float* __restrict__ g1, const float* __restrict__ b1v,
        const float* __restrict__ g2, const float* __restrict__ b2v)
{
    extern __shared__ __half smh[];
    const uint32_t smu = smem_u32(smh);
    float* red = (float*)smh;          // [128][4] sums + [128][4] sumsq = 4KB

    const int tid  = threadIdx.x;
    const int lane = tid & 31;
    const int w    = tid >> 5;
    const int wm   = w & 1;
    const int wn   = w >> 1;           // 0..3
    const int bm   = blockIdx.y * 128;

    // staging: A row = tid>>1 (4 chunks), B row = tid (8 chunks)
    const __half* Ap = A  + (long)(bm + (tid >> 1)) * D_ + (tid & 1) * 32;
    const __half* Bp = Bm + (long)tid * D_;
    uint32_t adsw[4], bdsw[8];
    #pragma unroll
    for (int j = 0; j < 4; j++)
        adsw[j] = swz((tid >> 1) * 128 + ((tid & 1) * 4 + j) * 16);
    #pragma unroll
    for (int j = 0; j < 8; j++) bdsw[j] = 16384 + swz(tid * 128 + j * 16);

    const int g = lane >> 2;
    const int c = lane & 3;

    float acc[4][8][4];
    #pragma unroll
    for (int i = 0; i < 4; i++)
        #pragma unroll
        for (int j = 0; j < 8; j++)
            #pragma unroll
            for (int r = 0; r < 4; r++) acc[i][j][r] = 0.0f;

    // prologue
    #pragma unroll
    for (int j = 0; j < 4; j++) cp16(smu + adsw[j], Ap + j * 8);
    #pragma unroll
    for (int j = 0; j < 8; j++) cp16(smu + bdsw[j], Bp + j * 8);
    cp_commit();

    int buf = 0;
    #pragma unroll
    for (int s = 0; s < 4; s++) {
        if (s < 3) {
            const int kn = (s + 1) << 6;
            const uint32_t base = smu + (buf ^ 1) * 49152;
            #pragma unroll
            for (int j = 0; j < 4; j++) cp16(base + adsw[j], Ap + kn + j * 8);
            #pragma unroll
            for (int j = 0; j < 8; j++) cp16(base + bdsw[j], Bp + kn + j * 8);
            cp_commit();
            asm volatile("cp.async.wait_group 1;" ::: "memory");
        } else {
            asm volatile("cp.async.wait_group 0;" ::: "memory");
        }
        __syncthreads();

        const uint32_t base = smu + buf * 49152;
        #pragma unroll
        for (int kb = 0; kb < 4; kb++) {
            uint32_t af[4][4];
            uint32_t bf[8][2];
            #pragma unroll
            for (int ma = 0; ma < 4; ma++)
                ldm4(af[ma], base +
                     swz((wm * 64 + ma * 16 + (lane & 15)) * 128 + kb * 32 + (lane >> 4) * 16));
            #pragma unroll
            for (int np = 0; np < 4; np++) {
                uint32_t t[4];
                ldm4(t, base + 16384 +
                        swz((wn * 64 + np * 16 + (lane & 15)) * 128 + kb * 32 + (lane >> 4) * 16));
                bf[2*np][0]   = t[0];
                bf[2*np+1][0] = t[1];
                bf[2*np][1]   = t[2];
                bf[2*np+1][1] = t[3];
            }
            #pragma unroll
            for (int ma = 0; ma < 4; ma++)
                #pragma unroll
                for (int nb = 0; nb < 8; nb++)
                    mma_f16(acc[ma][nb], af[ma], bf[nb]);
        }
        __syncthreads();
        buf ^= 1;
    }

    // ================= epilogue with fused LayerNorm(s) =================
    const int colb = wn * 64 + c * 2;      // + nb*8
    float2 biasv[8];
    #pragma unroll
    for (int nb = 0; nb < 8; nb++) biasv[nb] = *(const float2*)(bias + colb + nb * 8);

    #pragma unroll
    for (int ma = 0; ma < 4; ma++) {
        const long r0 = bm + wm * 64 + ma * 16 + g;
        #pragma unroll
        for (int nb = 0; nb < 8; nb++) {
            acc[ma][nb][0] += biasv[nb].x; acc[ma][nb][1] += biasv[nb].y;
            acc[ma][nb][2] += biasv[nb].x; acc[ma][nb][3] += biasv[nb].y;
            if (MODE == 7) {
                float2 ra = *(const float2*)(res32 + r0 * D_ + colb + nb * 8);
                float2 rb = *(const float2*)(res32 + (r0 + 8) * D_ + colb + nb * 8);
                acc[ma][nb][0] += ra.x; acc[ma][nb][1] += ra.y;
                acc[ma][nb][2] += rb.x; acc[ma][nb][3] += rb.y;
            }
        }
    }

    float mean0[4], inv0[4], mean1[4], inv1[4];
    auto reduce_rows = [&]() {
        #pragma unroll
        for (int ma = 0; ma < 4; ma++) {
            float s0 = 0, q0 = 0, s1 = 0, q1 = 0;
            #pragma unroll
            for (int nb = 0; nb < 8; nb++) {
                s0 += acc[ma][nb][0] + acc[ma][nb][1];
                q0 += acc[ma][nb][0] * acc[ma][nb][0] + acc[ma][nb][1] * acc[ma][nb][1];
                s1 += acc[ma][nb][2] + acc[ma][nb][3];
                q1 += acc[ma][nb][2] * acc[ma][nb][2] + acc[ma][nb][3] * acc[ma][nb][3];
            }
            s0 += __shfl_xor_sync(0xffffffffu, s0, 1); s0 += __shfl_xor_sync(0xffffffffu, s0, 2);
            q0 += __shfl_xor_sync(0xffffffffu, q0, 1); q0 += __shfl_xor_sync(0xffffffffu, q0, 2);
            s1 += __shfl_xor_sync(0xffffffffu, s1, 1); s1 += __shfl_xor_sync(0xffffffffu, s1, 2);
            q1 += __shfl_xor_sync(0xffffffffu, q1, 1); q1 += __shfl_xor_sync(0xffffffffu, q1, 2);
            if (c == 0) {
                const int r = wm * 64 + ma * 16 + g;
                red[r * 4 + wn]       = s0;  red[512 + r * 4 + wn]       = q0;
                red[(r + 8) * 4 + wn] = s1;  red[512 + (r + 8) * 4 + wn] = q1;
            }
        }
        __syncthreads();
        #pragma unroll
        for (int ma = 0; ma < 4; ma++) {
            const int r = wm * 64 + ma * 16 + g;
            float s0 = red[r*4] + red[r*4+1] + red[r*4+2] + red[r*4+3];
            float q0 = red[512+r*4] + red[512+r*4+1] + red[512+r*4+2] + red[512+r*4+3];
            float s1 = red[(r+8)*4] + red[(r+8)*4+1] + red[(r+8)*4+2] + red[(r+8)*4+3];
            float q1 = red[512+(r+8)*4] + red[512+(r+8)*4+1] + red[512+(r+8)*4+2] + red[512+(r+8)*4+3];
            mean0[ma] = s0 * (1.0f / 256.0f);
            inv0[ma]  = rsqrtf(q0 * (1.0f / 256.0f) - mean0[ma] * mean0[ma] + 1e-5f);
            mean1[ma] = s1 * (1.0f / 256.0f);
            inv1[ma]  = rsqrtf(q1 * (1.0f / 256.0f) - mean1[ma] * mean1[ma] + 1e-5f);
        }
        __syncthreads();
    };

    __syncthreads();
    if (MODE == 7 && g1 == nullptr) {
        #pragma unroll
        for (int ma = 0; ma < 4; ma++) {
            const long r0 = bm + wm * 64 + ma * 16 + g;
            #pragma unroll
            for (int nb = 0; nb < 8; nb++) {
                st2(xo + r0 * D_ + colb + nb * 8,       acc[ma][nb][0], acc[ma][nb][1]);
                st2(xo + (r0 + 8) * D_ + colb + nb * 8, acc[ma][nb][2], acc[ma][nb][3]);
            }
        }
        return;
    }

    reduce_rows();   // stats of t (MODE 6) or x (MODE 7)

    float2 g1v[8], b1vv[8];
    #pragma unroll
    for (int nb = 0; nb < 8; nb++) {
        g1v[nb]  = *(const float2*)(g1 + colb + nb * 8);
        b1vv[nb] = *(const float2*)(b1v + colb + nb * 8);
    }

    if (MODE == 7) {
        #pragma unroll
        for (int ma = 0; ma < 4; ma++) {
            const long r0 = bm + wm * 64 + ma * 16 + g;
            #pragma unroll
            for (int nb = 0; nb < 8; nb++) {
                const int cc = colb + nb * 8;
                float x0 = acc[ma][nb][0], x1 = acc[ma][nb][1];
                float x2 = acc[ma][nb][2], x3 = acc[ma][nb][3];
                st2(xo + r0 * D_ + cc, x0, x1);
                st2(xo + (r0 + 8) * D_ + cc, x2, x3);
                float h0 = (x0 - mean0[ma]) * inv0[ma] * g1v[nb].x + b1vv[nb].x;
                float h1 = (x1 - mean0[ma]) * inv0[ma] * g1v[nb].y + b1vv[nb].y;
                float h2 = (x2 - mean1[ma]) * inv1[ma] * g1v[nb].x + b1vv[nb].x;
                float h3 = (x3 - mean1[ma]) * inv1[ma] * g1v[nb].y + b1vv[nb].y;
                st2(out32 + r0 * D_ + cc, h0, h1);
                st2(out32 + (r0 + 8) * D_ + cc, h2, h3);
                st2(out16 + r0 * D_ + cc, h0, h1);
                st2(out16 + (r0 + 8) * D_ + cc, h2, h3);
            }
        }
        return;
    }

    // MODE 6: x = h32 + LN(t); second LN for C16
    #pragma unroll
    for (int ma = 0; ma < 4; ma++) {
        const long r0 = bm + wm * 64 + ma * 16 + g;
        #pragma unroll
        for (int nb = 0; nb < 8; nb++) {
            const int cc = colb + nb * 8;
            float2 ha = *(const float2*)(res32 + r0 * D_ + cc);
            float2 hb = *(const float2*)(res32 + (r0 + 8) * D_ + cc);
            acc[ma][nb][0] = ha.x + (acc[ma][nb][0] - mean0[ma]) * inv0[ma] * g1v[nb].x + b1vv[nb].x;
            acc[ma][nb][1] = ha.y + (acc[ma][nb][1] - mean0[ma]) * inv0[ma] * g1v[nb].y + b1vv[nb].y;
            acc[ma][nb][2] = hb.x + (acc[ma][nb][2] - mean1[ma]) * inv1[ma] * g1v[nb].x + b1vv[nb].x;
            acc[ma][nb][3] = hb.y + (acc[ma][nb][3] - mean1[ma]) * inv1[ma] * g1v[nb].y + b1vv[nb].y;
        }
    }
    reduce_rows();   // stats of x

    #pragma unroll
    for (int nb = 0; nb < 8; nb++) {
        g1v[nb]  = *(const float2*)(g2 + colb + nb * 8);
        b1vv[nb] = *(const float2*)(b2v + colb + nb * 8);
    }
    #pragma unroll
    for (int ma = 0; ma < 4; ma++) {
        const long r0 = bm + wm * 64 + ma * 16 + g;
        #pragma unroll
        for (int nb = 0; nb < 8; nb++) {
            const int cc = colb + nb * 8;
            float x0 = acc[ma][nb][0], x1 = acc[ma][nb][1];
            float x2 = acc[ma][nb][2], x3 = acc[ma][nb][3];
            st2(xo + r0 * D_ + cc, x0, x1);
            st2(xo + (r0 + 8) * D_ + cc, x2, x3);
            float c0 = (x0 - mean0[ma]) * inv0[ma] * g1v[nb].x + b1vv[nb].x;
            float c1 = (x1 - mean0[ma]) * inv0[ma] * g1v[nb].y + b1vv[nb].y;
            float c2 = (x2 - mean1[ma]) * inv1[ma] * g1v[nb].x + b1vv[nb].x;
            float c3 = (x3 - mean1[ma]) * inv1[ma] * g1v[nb].y + b1vv[nb].y;
            st2(out16 + r0 * D_ + cc, c0, c1);
            st2(out16 + (r0 + 8) * D_ + cc, c2, c3);
        }
    }
}
#define WSMEM 98304

// ---------------------------------------------------------------------------
// Launcher
// ---------------------------------------------------------------------------
extern "C" void kernel_launch(void* const* d_in, const int* in_sizes, int n_in,
                              void* d_out, int out_size)
{
    const float* x    = (const float*)d_in[0];
    const int*   mask = (const int*)  d_in[1];
    const float* btab = (const float*)d_in[2];
    const float* ln_g = (const float*)d_in[3];
    const float* ln_b = (const float*)d_in[4];
    const float* wq   = (const float*)d_in[5];
    const float* bq   = (const float*)d_in[6];
    const float* wk   = (const float*)d_in[7];
    const float* bk   = (const float*)d_in[8];
    const float* wv   = (const float*)d_in[9];
    const float* bv   = (const float*)d_in[10];
    const float* wo   = (const float*)d_in[11];
    const float* bo   = (const float*)d_in[12];
    const float* cmg  = (const float*)d_in[13];
    const float* cmb  = (const float*)d_in[14];
    const float* w1   = (const float*)d_in[15];
    const float* b1   = (const float*)d_in[16];
    const float* w2   = (const float*)d_in[17];
    const float* b2   = (const float*)d_in[18];
    float* xo = (float*)d_out;

    __half *H16, *Q16, *K16, *V16, *O16, *C16, *F16, *WT, *WQKV;
    float *H32;
    cudaGetSymbolAddress((void**)&H16,  g_H16);
    cudaGetSymbolAddress((void**)&Q16,  g_Q16);
    cudaGetSymbolAddress((void**)&K16,  g_K16);
    cudaGetSymbolAddress((void**)&V16,  g_V16);
    cudaGetSymbolAddress((void**)&O16,  g_O16);
    cudaGetSymbolAddress((void**)&C16,  g_C16);
    cudaGetSymbolAddress((void**)&F16,  g_F16);
    cudaGetSymbolAddress((void**)&WT,   g_WT16);
    cudaGetSymbolAddress((void**)&WQKV, g_WQKV);
    cudaGetSymbolAddress((void**)&H32,  g_H32);

    cudaFuncSetAttribute(gemm_k<5, __half>, cudaFuncAttributeMaxDynamicSharedMemorySize, GSMEM);
    cudaFuncSetAttribute(gemm_k<2, __half>, cudaFuncAttributeMaxDynamicSharedMemorySize, GSMEM);
    cudaFuncSetAttribute(gemmw_k<6>, cudaFuncAttributeMaxDynamicSharedMemorySize, WSMEM);
    cudaFuncSetAttribute(gemmw_k<7>, cudaFuncAttributeMaxDynamicSharedMemorySize, WSMEM);
    cudaFuncSetAttribute(flash_k, cudaFuncAttributeMaxDynamicSharedMemorySize, FSMEM);

    // one-time weight transposes (fp32 -> fp16, transposed)
    const dim3 trWg(8, 8, 3), trB(32, 8);
    trW_k<<<trWg, trB>>>(wq, WQKV + 0L * WSZ, D_, D_, 3L * WSZ);
    trW_k<<<trWg, trB>>>(wk, WQKV + 1L * WSZ, D_, D_, 3L * WSZ);
    trW_k<<<trWg, trB>>>(wv, WQKV + 2L * WSZ, D_, D_, 3L * WSZ);
    trW_k<<<trWg, trB>>>(wo, WT + 0L * 3 * WSZ, D_, D_, WSZ);
    trW_k<<<trWg, trB>>>(w1, WT + 1L * 3 * WSZ, D_, D_, WSZ);
    trW_k<<<trWg, trB>>>(w2, WT + 2L * 3 * WSZ, D_, D_, WSZ);

    const dim3 gQKV(6, ROWS / 128, 1);
    const dim3 gProj(D_ / 128, ROWS / 128, 1);
    const dim3 gWide(1, ROWS / 128, 1);          // 256 CTAs (M=128 tiles)
    const dim3 gFlash(S_ / 64, 1, B_);           // 64-row blocks x batches
    const int  rowBlocks = ROWS / 8;

    // layer-0 input LN
    ln_k<<<rowBlocks, 256>>>(x, ln_g, ln_b, H16, H32, ROWS);

    for (int j = 0; j < 3; j++) {
        const float* gj = ln_g + j * D_;
        const float* bj = ln_b + j * D_;
        const __half* wqkvT = WQKV + (long)j * 3 * WSZ;
        const __half* woT   = WT + (0L * 3 + j) * WSZ;
        const __half* w1T   = WT + (1L * 3 + j) * WSZ;
        const __half* w2T   = WT + (2L * 3 + j) * WSZ;

        // q,k,v = h @ {wq,wk,wv} + bias (fused, routed)
        gemm_k<5, __half><<<gQKV, 128, GSMEM>>>(H16, wqkvT, bq + j * D_, Q16,
                                                ROWS, 768, D_,
                                                K16, V16, bk + j * D_, bv + j * D_);

        // o = attention(q, k, v)  — no QK^T duplication
        flash_k<<<gFlash, 256, FSMEM>>>(Q16, K16, V16, mask, btab, O16);

        // x = h + LN(o@wo+bo); c = LN_cm(x)   (fused wide GEMM)
        gemmw_k<6><<<gWide, 256, WSMEM>>>(O16, woT, bo + j * D_, H32,
                                          xo, C16, nullptr,
                                          gj, bj, cmg + j * D_, cmb + j * D_);

        // f = gelu(c @ w1 + b1)
        gemm_k<2, __half><<<gProj, 128, GSMEM>>>(C16, w1T, b1 + j * D_, F16,
                                                 ROWS, D_, D_,
                                                 (__half*)nullptr, (__half*)nullptr, nullptr, nullptr);

        // x = x + f@w2 + b2 ; h_next = LN(x) (layers 0,1)
        const bool last = (j == 2);
        gemmw_k<7><<<gWide, 256, WSMEM>>>(F16, w2T, b2 + j * D_, xo,
                                          xo, last ? nullptr : H16,
                                          last ? nullptr : H32,
                                          last ? nullptr : ln_g + (j + 1) * D_,
                                          last ? nullptr : ln_b + (j + 1) * D_,
                                          nullptr, nullptr);
    }
}

// round 16
// speedup vs baseline: 1.2783x; 1.0144x over previous
#include <cuda_runtime.h>
#include <cuda_fp16.h>
#include <math.h>
#include <stdint.h>

// Problem dims (fixed)
#define B_   64
#define S_   512
#define D_   256
#define ROWS (B_ * S_)          // 32768
#define WSZ  (D_ * D_)          // 65536 per-layer weight size
#define L2E  1.4426950408889634f

// ---------------------------------------------------------------------------
// Scratch (device globals; no allocation allowed)
// ---------------------------------------------------------------------------
__device__ __half g_H16[ROWS * D_];
__device__ __half g_Q16[ROWS * D_];
__device__ __half g_K16[ROWS * D_];
__device__ __half g_V16[ROWS * D_];
__device__ __half g_O16[ROWS * D_];
__device__ __half g_C16[ROWS * D_];
__device__ __half g_F16[ROWS * D_];
__device__ __half g_WT16[3 * 3 * WSZ];        // wo,w1,w2 transposed fp16
__device__ __half g_WQKV[3 * 3 * WSZ];        // per-layer [768][256] fp16
__device__ float  g_H32[ROWS * D_];           // LN(x) fp32 (residual use)

// ---------------------------------------------------------------------------
// helpers
// ---------------------------------------------------------------------------
__device__ __forceinline__ uint32_t smem_u32(const void* p) {
    uint32_t a;
    asm("{ .reg .u64 t; cvta.to.shared.u64 t, %1; cvt.u32.u64 %0, t; }"
        : "=r"(a) : "l"(p));
    return a;
}
__device__ __forceinline__ uint32_t swz(uint32_t byte) {   // SW128
    return byte ^ ((byte >> 3) & 0x70);
}
__device__ __forceinline__ void cp16(uint32_t dst, const void* src) {
    asm volatile("cp.async.cg.shared.global [%0], [%1], 16;"
                 :: "r"(dst), "l"(src) : "memory");
}
__device__ __forceinline__ void cp_commit() {
    asm volatile("cp.async.commit_group;" ::: "memory");
}
__device__ __forceinline__ void ldm4(uint32_t* r, uint32_t a) {
    asm volatile("ldmatrix.sync.aligned.m8n8.x4.shared.b16 {%0,%1,%2,%3}, [%4];"
                 : "=r"(r[0]), "=r"(r[1]), "=r"(r[2]), "=r"(r[3]) : "r"(a));
}
__device__ __forceinline__ void ldm4t(uint32_t* r, uint32_t a) {
    asm volatile("ldmatrix.sync.aligned.m8n8.x4.trans.shared.b16 {%0,%1,%2,%3}, [%4];"
                 : "=r"(r[0]), "=r"(r[1]), "=r"(r[2]), "=r"(r[3]) : "r"(a));
}
__device__ __forceinline__ void mma_f16(float* d, const uint32_t* a, const uint32_t* b) {
    asm volatile(
        "mma.sync.aligned.m16n8k16.row.col.f32.f16.f16.f32 "
        "{%0,%1,%2,%3}, {%4,%5,%6,%7}, {%8,%9}, {%0,%1,%2,%3};"
        : "+f"(d[0]), "+f"(d[1]), "+f"(d[2]), "+f"(d[3])
        : "r"(a[0]), "r"(a[1]), "r"(a[2]), "r"(a[3]), "r"(b[0]), "r"(b[1]));
}
__device__ __forceinline__ float ex2(float x) {    // single MUFU.EX2
    float r;
    asm("ex2.approx.f32 %0, %1;" : "=f"(r) : "f"(x));
    return r;
}
__device__ __forceinline__ float frcp(float x) {   // single MUFU.RCP
    float r;
    asm("rcp.approx.f32 %0, %1;" : "=f"(r) : "f"(x));
    return r;
}
__device__ __forceinline__ void st2(float* p, float a, float b) {
    *(float2*)p = make_float2(a, b);
}
__device__ __forceinline__ void st2(__half* p, float a, float b) {
    *(__half2*)p = __floats2half2_rn(a, b);
}

// ---------------------------------------------------------------------------
// Weight transpose (3 weights per launch, routed by blockIdx.z):
//   widx = z / perW, j = z % perW; in = inX + j*rows*cols;
//   out = outbase + widx*wstride + j*zstride; out[c][r] = in[r][c] (fp16)
// ---------------------------------------------------------------------------
__global__ void trW3_k(const float* __restrict__ i0, const float* __restrict__ i1,
                       const float* __restrict__ i2, __half* __restrict__ outbase,
                       long wstride, long zstride, int perW, int rows, int cols)
{
    __shared__ float t[32][33];
    const int widx = blockIdx.z / perW;
    const int j    = blockIdx.z % perW;
    const float* in = (widx == 0 ? i0 : (widx == 1 ? i1 : i2)) + (long)j * rows * cols;
    __half* out = outbase + widx * wstride + j * zstride;

    const int r0 = blockIdx.y * 32, c0 = blockIdx.x * 32;
    const int tx = threadIdx.x, ty = threadIdx.y;
    #pragma unroll
    for (int i = 0; i < 32; i += 8)
        t[ty + i][tx] = in[(long)(r0 + ty + i) * cols + c0 + tx];
    __syncthreads();
    #pragma unroll
    for (int i = 0; i < 32; i += 8)
        out[(long)(c0 + ty + i) * rows + r0 + tx] = __float2half_rn(t[tx][ty + i]);
}

// ---------------------------------------------------------------------------
// LayerNorm (used once, layer 0 input): one warp per row -> H16 + H32
// ---------------------------------------------------------------------------
__global__ void ln_k(const float* __restrict__ in,
                     const float* __restrict__ g, const float* __restrict__ b,
                     __half* __restrict__ out16, float* __restrict__ out32, int rows)
{
    int warp = (blockIdx.x * blockDim.x + threadIdx.x) >> 5;
    int lane = threadIdx.x & 31;
    if (warp >= rows) return;

    const float4* x4 = (const float4*)(in + (long)warp * D_);
    float4 v0 = x4[lane];
    float4 v1 = x4[lane + 32];

    float s = v0.x + v0.y + v0.z + v0.w + v1.x + v1.y + v1.z + v1.w;
    #pragma unroll
    for (int o = 16; o; o >>= 1) s += __shfl_xor_sync(0xffffffffu, s, o);
    float mean = s * (1.0f / 256.0f);

    float d0x = v0.x - mean, d0y = v0.y - mean, d0z = v0.z - mean, d0w = v0.w - mean;
    float d1x = v1.x - mean, d1y = v1.y - mean, d1z = v1.z - mean, d1w = v1.w - mean;
    float q = d0x*d0x + d0y*d0y + d0z*d0z + d0w*d0w
            + d1x*d1x + d1y*d1y + d1z*d1z + d1w*d1w;
    #pragma unroll
    for (int o = 16; o; o >>= 1) q += __shfl_xor_sync(0xffffffffu, q, o);
    float inv = rsqrtf(q * (1.0f / 256.0f) + 1e-5f);

    const float4* g4 = (const float4*)g;
    const float4* b4 = (const float4*)b;
    float4 gv0 = g4[lane], gv1 = g4[lane + 32];
    float4 bv0 = b4[lane], bv1 = b4[lane + 32];

    float4 o0, o1;
    o0.x = d0x * inv * gv0.x + bv0.x;  o0.y = d0y * inv * gv0.y + bv0.y;
    o0.z = d0z * inv * gv0.z + bv0.z;  o0.w = d0w * inv * gv0.w + bv0.w;
    o1.x = d1x * inv * gv1.x + bv1.x;  o1.y = d1y * inv * gv1.y + bv1.y;
    o1.z = d1z * inv * gv1.z + bv1.z;  o1.w = d1w * inv * gv1.w + bv1.w;

    float4* out4 = (float4*)(out32 + (long)warp * D_);
    out4[lane]      = o0;
    out4[lane + 32] = o1;
    __half2* oh = (__half2*)(out16 + (long)warp * D_);
    oh[lane * 2]            = __floats2half2_rn(o0.x, o0.y);
    oh[lane * 2 + 1]        = __floats2half2_rn(o0.z, o0.w);
    oh[(lane + 32) * 2]     = __floats2half2_rn(o1.x, o1.y);
    oh[(lane + 32) * 2 + 1] = __floats2half2_rn(o1.z, o1.w);
}

// ---------------------------------------------------------------------------
// Fused flash attention v2.1 — no QK^T duplication; restructured sync:
//  - Q staged into the KV1 region CONCURRENTLY with KV tile-0 into KV0.
//  - stageKV(t+1) issued after the top barrier -> trailing barrier removed
//    (buffer-reuse safety comes from the next tile's top barrier).
// CTA = 64 q-rows x full 256 D. 8 warps: wr = w&3, wc = w>>2.
// smem: btab [0,4K) | P [4K,12K) | lsum [12K,12.5K) | KV0 @13312 | KV1 @78848
// ---------------------------------------------------------------------------
__global__ void __launch_bounds__(256)
flash_k(const __half* __restrict__ Qg, const __half* __restrict__ Kg,
        const __half* __restrict__ Vg, const int* __restrict__ mask,
        const float* __restrict__ btab, __half* __restrict__ Og)
{
    extern __shared__ char sm[];
    const uint32_t smu = smem_u32(sm);
    float* btab_s = (float*)sm;
    float* lsum   = (float*)(sm + 12288);
    const uint32_t Pu  = smu + 4096;
    const uint32_t KV0 = smu + 13312;
    const uint32_t KV1 = KV0 + 65536;

    const int tid = threadIdx.x, lane = tid & 31, w = tid >> 5;
    const int wr = w & 3, wc = w >> 2;
    const int r0 = blockIdx.x * 64, bz = blockIdx.z;

    const __half* Qp = Qg + ((long)bz * S_ + r0) * D_;
    const __half* Kp = Kg + (long)bz * S_ * D_;
    const __half* Vp = Vg + (long)bz * S_ * D_;
    __half* Op = Og + ((long)bz * S_ + r0) * D_;
    const int* mk = mask + bz * S_;

    ((float4*)btab_s)[tid] = ((const float4*)btab)[tid];

    const int sr = tid >> 2, sch = tid & 3;

    auto stageKV = [&](int t, int bf) {
        const __half* ks = Kp + (long)(t * 64 + sr) * D_;
        const __half* vs = Vp + (long)(t * 64 + sr) * D_;
        const uint32_t kd = bf ? KV1 : KV0;
        const uint32_t vd = kd + 32768;
        #pragma unroll
        for (int p = 0; p < 4; p++) {
            cp16(kd + p * 8192 + swz(sr * 128 + sch * 16),       ks + p * 64 + sch * 8);
            cp16(kd + p * 8192 + swz(sr * 128 + (sch + 4) * 16), ks + p * 64 + (sch + 4) * 8);
            cp16(vd + p * 8192 + swz(sr * 128 + sch * 16),       vs + p * 64 + sch * 8);
            cp16(vd + p * 8192 + swz(sr * 128 + (sch + 4) * 16), vs + p * 64 + (sch + 4) * 8);
        }
    };

    // ---- stage Q (32KB, into KV1 region) || KV tile 0 (into KV0) ----
    {
        const __half* src = Qp + (long)sr * D_;
        #pragma unroll
        for (int p = 0; p < 4; p++) {
            cp16(KV1 + p * 8192 + swz(sr * 128 + sch * 16),       src + p * 64 + sch * 8);
            cp16(KV1 + p * 8192 + swz(sr * 128 + (sch + 4) * 16), src + p * 64 + (sch + 4) * 8);
        }
        cp_commit();                   // group: Q
    }
    stageKV(0, 0); cp_commit();        // group: KV0

    asm volatile("cp.async.wait_group 1;" ::: "memory");   // Q done (KV0 may pend)
    __syncthreads();

    uint32_t qf[16][4];
    {
        const int qrow = wr * 16 + (lane & 15);
        #pragma unroll
        for (int kt = 0; kt < 16; kt++)
            ldm4(qf[kt], KV1 + (kt >> 2) * 8192 +
                         swz(qrow * 128 + (kt & 3) * 32 + (lane >> 4) * 16));
    }
    __syncthreads();   // Q reads done before tile-1 staging overwrites KV1

    const int g = lane >> 2, c = lane & 3;
    const int rowg = r0 + wr * 16 + g;
    const int kb8 = (lane >> 3) & 1, nb8 = lane >> 4, li = lane & 7;

    float oacc[16][4];
    #pragma unroll
    for (int i = 0; i < 16; i++)
        #pragma unroll
        for (int r = 0; r < 4; r++) oacc[i][r] = 0.0f;
    float l0 = 0.0f, l1 = 0.0f;

    for (int t = 0; t < 8; t++) {
        const int bf = t & 1;
        asm volatile("cp.async.wait_group 0;" ::: "memory");  // tile t staged
        __syncthreads();                                      // + all t-1 reads done

        if (t < 7) { stageKV(t + 1, bf ^ 1); cp_commit(); }   // safe: t-1 readers done

        // ---- S = Q K^T : 16 rows x 32 keys (warp's key half) ----
        float sacc[4][4];
        #pragma unroll
        for (int i = 0; i < 4; i++)
            #pragma unroll
            for (int r = 0; r < 4; r++) sacc[i][r] = 0.0f;
        const uint32_t Kb = bf ? KV1 : KV0;
        #pragma unroll
        for (int kt = 0; kt < 16; kt++) {
            #pragma unroll
            for (int np = 0; np < 2; np++) {
                uint32_t tt[4];
                ldm4(tt, Kb + (kt >> 2) * 8192 +
                         swz((wc * 32 + np * 16 + (lane & 15)) * 128 +
                             (kt & 3) * 32 + (lane >> 4) * 16));
                uint32_t b0[2] = {tt[0], tt[2]}, b1[2] = {tt[1], tt[3]};
                mma_f16(sacc[2 * np],     qf[kt], b0);
                mma_f16(sacc[2 * np + 1], qf[kt], b1);
            }
        }

        // ---- p = exp(s + bias), masked -> 0 ; accumulate partials ----
        #pragma unroll
        for (int nt = 0; nt < 4; nt++) {
            const int n = t * 64 + wc * 32 + nt * 8 + c * 2;
            const int mk0 = mk[n], mk1 = mk[n + 1];
            int rel, bk;
            rel = n - rowg;           bk = rel < 0 ? 511 - rel : rel;
            float s00 = fmaf(sacc[nt][0], 0.0625f, btab_s[bk]);
            rel = n + 1 - rowg;       bk = rel < 0 ? 511 - rel : rel;
            float s01 = fmaf(sacc[nt][1], 0.0625f, btab_s[bk]);
            rel = n - (rowg + 8);     bk = rel < 0 ? 511 - rel : rel;
            float s10 = fmaf(sacc[nt][2], 0.0625f, btab_s[bk]);
            rel = n + 1 - (rowg + 8); bk = rel < 0 ? 511 - rel : rel;
            float s11 = fmaf(sacc[nt][3], 0.0625f, btab_s[bk]);
            float p00 = mk0 ? ex2(s00 * L2E) : 0.0f;
            float p01 = mk1 ? ex2(s01 * L2E) : 0.0f;
            float p10 = mk0 ? ex2(s10 * L2E) : 0.0f;
            float p11 = mk1 ? ex2(s11 * L2E) : 0.0f;
            l0 += p00 + p01;
            l1 += p10 + p11;
            sacc[nt][0] = p00; sacc[nt][1] = p01; sacc[nt][2] = p10; sacc[nt][3] = p11;
        }

        // ---- store P (fp16) to smem panel [64 rows][64 keys] ----
        #pragma unroll
        for (int nt = 0; nt < 4; nt++) {
            const int cc = wc * 32 + nt * 8 + c * 2;
            *(__half2*)(sm + 4096 + swz((wr * 16 + g) * 128 + cc * 2)) =
                __floats2half2_rn(sacc[nt][0], sacc[nt][1]);
            *(__half2*)(sm + 4096 + swz((wr * 16 + g + 8) * 128 + cc * 2)) =
                __floats2half2_rn(sacc[nt][2], sacc[nt][3]);
        }
        __syncthreads();   // P visible to all warps

        // ---- O += P @ V : 16 rows x 128 cols (warp's col half) ----
        const uint32_t Vb = (bf ? KV1 : KV0) + 32768;
        #pragma unroll
        for (int pk = 0; pk < 4; pk++) {
            uint32_t af[4];
            ldm4(af, Pu + swz((wr * 16 + (lane & 15)) * 128 + pk * 32 + (lane >> 4) * 16));
            #pragma unroll
            for (int nv = 0; nv < 8; nv++) {
                uint32_t tt[4];
                const int vp = wc * 2 + (nv >> 2);
                ldm4t(tt, Vb + vp * 8192 +
                          swz((pk * 16 + kb8 * 8 + li) * 128 + (nv & 3) * 32 + nb8 * 16));
                uint32_t b0[2] = {tt[0], tt[1]}, b1[2] = {tt[2], tt[3]};
                mma_f16(oacc[2 * nv],     af, b0);
                mma_f16(oacc[2 * nv + 1], af, b1);
            }
        }
        // no trailing sync: next tile's top barrier orders P/V reuse
    }

    // ---- final l reduction: across c (shfl) then across wc (smem) ----
    l0 += __shfl_xor_sync(0xffffffffu, l0, 1);
    l0 += __shfl_xor_sync(0xffffffffu, l0, 2);
    l1 += __shfl_xor_sync(0xffffffffu, l1, 1);
    l1 += __shfl_xor_sync(0xffffffffu, l1, 2);
    __syncthreads();   // all PV reads done before lsum reuse of smem region
    if (c == 0) {
        lsum[(wr * 16 + g) * 2 + wc]     = l0;
        lsum[(wr * 16 + g + 8) * 2 + wc] = l1;
    }
    __syncthreads();
    const float rc0 = frcp(lsum[(wr * 16 + g) * 2]     + lsum[(wr * 16 + g) * 2 + 1]);
    const float rc1 = frcp(lsum[(wr * 16 + g + 8) * 2] + lsum[(wr * 16 + g + 8) * 2 + 1]);

    #pragma unroll
    for (int nt = 0; nt < 16; nt++) {
        const int col = wc * 128 + nt * 8 + c * 2;
        st2(Op + (long)(wr * 16 + g) * D_ + col,     oacc[nt][0] * rc0, oacc[nt][1] * rc0);
        st2(Op + (long)(wr * 16 + g + 8) * D_ + col, oacc[nt][2] * rc1, oacc[nt][3] * rc1);
    }
}
#define FSMEM 144384

// ---------------------------------------------------------------------------
// FP16 GEMM 128x128x64 — used for QKV (EPI 5) and w1+gelu (EPI 2).
// ---------------------------------------------------------------------------
template<int EPI, typename TO>
__global__ void __launch_bounds__(128, 2)
gemm_k(const __half* __restrict__ A, const __half* __restrict__ Bm,
       const float* bias, TO* C, int M, int N, int K,
       TO* C2, TO* C3, const float* bias2, const float* bias3)
{
    extern __shared__ __half smh[];
    const uint32_t smu = smem_u32(smh);

    const int tid  = threadIdx.x;
    const int lane = tid & 31;
    const int wm   = (tid >> 5) & 1;
    const int wn   = tid >> 6;
    const int bm = blockIdx.y * 128;
    const int bn = blockIdx.x * 128;

    if (EPI == 5) {
        const int sel = bn >> 8;
        if (sel == 1) { C = C2; bias = bias2; }
        else if (sel == 2) { C = C3; bias = bias3; }
    }
    const int No = (EPI == 5) ? 256 : N;

    const __half* Ap = A  + (long)(bm + tid) * K;
    const __half* Bp = Bm + (long)(bn + tid) * K;
    uint32_t dsw[8];
    #pragma unroll
    for (int j = 0; j < 8; j++) dsw[j] = swz(tid * 128 + j * 16);

    uint32_t arow[4], brow[4];
    #pragma unroll
    for (int i = 0; i < 4; i++) {
        arow[i] = (wm * 64 + i * 16 + (lane & 15)) * 128 + (lane >> 4) * 16;
        brow[i] = (wn * 64 + i * 16 + (lane & 15)) * 128 + (lane >> 4) * 16;
    }
    const int g = lane >> 2;
    const int c = lane & 3;

    float acc[4][8][4];
    #pragma unroll
    for (int i = 0; i < 4; i++)
        #pragma unroll
        for (int j = 0; j < 8; j++)
            #pragma unroll
            for (int r = 0; r < 4; r++) acc[i][j][r] = 0.0f;

    const int nst = K >> 6;

    #pragma unroll
    for (int j = 0; j < 8; j++) {
        cp16(smu + dsw[j],         Ap + j * 8);
        cp16(smu + 16384 + dsw[j], Bp + j * 8);
    }
    cp_commit();

    int buf = 0;
    for (int s = 0; s < nst; s++) {
        if (s + 1 < nst) {
            const int kn = (s + 1) << 6;
            const uint32_t base = smu + (buf ^ 1) * 32768;
            #pragma unroll
            for (int j = 0; j < 8; j++) {
                cp16(base + dsw[j],         Ap + kn + j * 8);
                cp16(base + 16384 + dsw[j], Bp + kn + j * 8);
            }
            cp_commit();
            asm volatile("cp.async.wait_group 1;" ::: "memory");
        } else {
            asm volatile("cp.async.wait_group 0;" ::: "memory");
        }
        __syncthreads();

        const uint32_t Au = smu + buf * 32768;
        const uint32_t Bu = Au + 16384;
        #pragma unroll
        for (int kb = 0; kb < 4; kb++) {
            uint32_t af[4][4];
            uint32_t bf[8][2];
            #pragma unroll
            for (int ma = 0; ma < 4; ma++)
                ldm4(af[ma], Au + swz(arow[ma] + kb * 32));
            #pragma unroll
            for (int np = 0; np < 4; np++) {
                uint32_t t[4];
                ldm4(t, Bu + swz(brow[np] + kb * 32));
                bf[2*np][0]   = t[0];
                bf[2*np+1][0] = t[1];
                bf[2*np][1]   = t[2];
                bf[2*np+1][1] = t[3];
            }
            #pragma unroll
            for (int ma = 0; ma < 4; ma++)
                #pragma unroll
                for (int nb = 0; nb < 8; nb++)
                    mma_f16(acc[ma][nb], af[ma], bf[nb]);
        }
        __syncthreads();
        buf ^= 1;
    }

    #pragma unroll
    for (int nb = 0; nb < 8; nb++) {
        const int col  = bn + wn * 64 + nb * 8 + c * 2;
        const int colo = (EPI == 5) ? (col & 255) : col;
        float2 bv = *(const float2*)(bias + colo);

        #pragma unroll
        for (int ma = 0; ma < 4; ma++) {
            const int r0 = bm + wm * 64 + ma * 16 + g;
            const int r1 = r0 + 8;
            float d0 = acc[ma][nb][0] + bv.x, d1 = acc[ma][nb][1] + bv.y;
            float d2 = acc[ma][nb][2] + bv.x, d3 = acc[ma][nb][3] + bv.y;
            if (EPI == 2) {
                d0 = 0.5f * d0 * (1.0f + erff(d0 * 0.70710678118654752f));
                d1 = 0.5f * d1 * (1.0f + erff(d1 * 0.70710678118654752f));
                d2 = 0.5f * d2 * (1.0f + erff(d2 * 0.70710678118654752f));
                d3 = 0.5f * d3 * (1.0f + erff(d3 * 0.70710678118654752f));
            }
            st2(C + (long)r0 * No + colo, d0, d1);
            st2(C + (long)r1 * No + colo, d2, d3);
        }
    }
}
#define GSMEM 65536

// ---------------------------------------------------------------------------
// WIDE GEMM 128x256x64: 256 threads (8 warps: wm=w&1, wn=w>>1), warp 64x64.
// MODE 6 (wo):  t = A@B + bias; x = h32 + LN_{g1,b1}(t); xo=x; C16=LN_{g2,b2}(x)
// MODE 7 (w2):  x = res32 + A@B + bias; xo=x; if g1: H=LN_{g1,b1}(x) -> h16,h32
// ---------------------------------------------------------------------------
template<int MODE>
__global__ void __launch_bounds__(256, 1)
gemmw_k(const __half* __restrict__ A, const __half* __restrict__ Bm,
        const float* __restrict__ bias, const float* __restrict__ res32,
        float* __restrict__ xo, __half* __restrict__ out16,
        float* __restrict__ out32,
        const float* __restrict__ g1, const float* __restrict__ b1v,
        const float* __restrict__ g2, const float* __restrict__ b2v)
{
    extern __shared__ __half smh[];
    const uint32_t smu = smem_u32(smh);
    float* red = (float*)smh;

    const int tid  = threadIdx.x;
    const int lane = tid & 31;
    const int w    = tid >> 5;
    const int wm   = w & 1;
    const int wn   = w >> 1;
    const int bm   = blockIdx.y * 128;

    const __half* Ap = A  + (long)(bm + (tid >> 1)) * D_ + (tid & 1) * 32;
    const __half* Bp = Bm + (long)tid * D_;
    uint32_t adsw[4], bdsw[8];
    #pragma unroll
    for (int j = 0; j < 4; j++)
        adsw[j] = swz((tid >> 1) * 128 + ((tid & 1) * 4 + j) * 16);
    #pragma unroll
    for (int j = 0; j < 8; j++) bdsw[j] = 16384 + swz(tid * 128 + j * 16);

    const int g = lane >> 2;
    const int c = lane & 3;

    float acc[4][8][4];
    #pragma unroll
    for (int i = 0; i < 4; i++)
        #pragma unroll
        for (int j = 0; j < 8; j++)
            #pragma unroll
            for (int r = 0; r < 4; r++) acc[i][j][r] = 0.0f;

    #pragma unroll
    for (int j = 0; j < 4; j++) cp16(smu + adsw[j], Ap + j * 8);
    #pragma unroll
    for (int j = 0; j < 8; j++) cp16(smu + bdsw[j], Bp + j * 8);
    cp_commit();

    int buf = 0;
    #pragma unroll
    for (int s = 0; s < 4; s++) {
        if (s < 3) {
            const int kn = (s + 1) << 6;
            const uint32_t base = smu + (buf ^ 1) * 49152;
            #pragma unroll
            for (int j = 0; j < 4; j++) cp16(base + adsw[j], Ap + kn + j * 8);
            #pragma unroll
            for (int j = 0; j < 8; j++) cp16(base + bdsw[j], Bp + kn + j * 8);
            cp_commit();
            asm volatile("cp.async.wait_group 1;" ::: "memory");
        } else {
            asm volatile("cp.async.wait_group 0;" ::: "memory");
        }
        __syncthreads();

        const uint32_t base = smu + buf * 49152;
        #pragma unroll
        for (int kb = 0; kb < 4; kb++) {
            uint32_t af[4][4];
            uint32_t bf[8][2];
            #pragma unroll
            for (int ma = 0; ma < 4; ma++)
                ldm4(af[ma], base +
                     swz((wm * 64 + ma * 16 + (lane & 15)) * 128 + kb * 32 + (lane >> 4) * 16));
            #pragma unroll
            for (int np = 0; np < 4; np++) {
                uint32_t t[4];
                ldm4(t, base + 16384 +
                        swz((wn * 64 + np * 16 + (lane & 15)) * 128 + kb * 32 + (lane >> 4) * 16));
                bf[2*np][0]   = t[0];
                bf[2*np+1][0] = t[1];
                bf[2*np][1]   = t[2];
                bf[2*np+1][1] = t[3];
            }
            #pragma unroll
            for (int ma = 0; ma < 4; ma++)
                #pragma unroll
                for (int nb = 0; nb < 8; nb++)
                    mma_f16(acc[ma][nb], af[ma], bf[nb]);
        }
        __syncthreads();
        buf ^= 1;
    }

    // ================= epilogue with fused LayerNorm(s) =================
    const int colb = wn * 64 + c * 2;
    float2 biasv[8];
    #pragma unroll
    for (int nb = 0; nb < 8; nb++) biasv[nb] = *(const float2*)(bias + colb + nb * 8);

    #pragma unroll
    for (int ma = 0; ma < 4; ma++) {
        const long r0 = bm + wm * 64 + ma * 16 + g;
        #pragma unroll
        for (int nb = 0; nb < 8; nb++) {
            acc[ma][nb][0] += biasv[nb].x; acc[ma][nb][1] += biasv[nb].y;
            acc[ma][nb][2] += biasv[nb].x; acc[ma][nb][3] += biasv[nb].y;
            if (MODE == 7) {
                float2 ra = *(const float2*)(res32 + r0 * D_ + colb + nb * 8);
                float2 rb = *(const float2*)(res32 + (r0 + 8) * D_ + colb + nb * 8);
                acc[ma][nb][0] += ra.x; acc[ma][nb][1] += ra.y;
                acc[ma][nb][2] += rb.x; acc[ma][nb][3] += rb.y;
            }
        }
    }

    float mean0[4], inv0[4], mean1[4], inv1[4];
    auto reduce_rows = [&]() {
        #pragma unroll
        for (int ma = 0; ma < 4; ma++) {
            float s0 = 0, q0 = 0, s1 = 0, q1 = 0;
            #pragma unroll
            for (int nb = 0; nb < 8; nb++) {
                s0 += acc[ma][nb][0] + acc[ma][nb][1];
                q0 += acc[ma][nb][0] * acc[ma][nb][0] + acc[ma][nb][1] * acc[ma][nb][1];
                s1 += acc[ma][nb][2] + acc[ma][nb][3];
                q1 += acc[ma][nb][2] * acc[ma][nb][2] + acc[ma][nb][3] * acc[ma][nb][3];
            }
            s0 += __shfl_xor_sync(0xffffffffu, s0, 1); s0 += __shfl_xor_sync(0xffffffffu, s0, 2);
            q0 += __shfl_xor_sync(0xffffffffu, q0, 1); q0 += __shfl_xor_sync(0xffffffffu, q0, 2);
            s1 += __shfl_xor_sync(0xffffffffu, s1, 1); s1 += __shfl_xor_sync(0xffffffffu, s1, 2);
            q1 += __shfl_xor_sync(0xffffffffu, q1, 1); q1 += __shfl_xor_sync(0xffffffffu, q1, 2);
            if (c == 0) {
                const int r = wm * 64 + ma * 16 + g;
                red[r * 4 + wn]       = s0;  red[512 + r * 4 + wn]       = q0;
                red[(r + 8) * 4 + wn] = s1;  red[512 + (r + 8) * 4 + wn] = q1;
            }
        }
        __syncthreads();
        #pragma unroll
        for (int ma = 0; ma < 4; ma++) {
            const int r = wm * 64 + ma * 16 + g;
            float s0 = red[r*4] + red[r*4+1] + red[r*4+2] + red[r*4+3];
            float q0 = red[512+r*4] + red[512+r*4+1] + red[512+r*4+2] + red[512+r*4+3];
            float s1 = red[(r+8)*4] + red[(r+8)*4+1] + red[(r+8)*4+2] + red[(r+8)*4+3];
            float q1 = red[512+(r+8)*4] + red[512+(r+8)*4+1] + red[512+(r+8)*4+2] + red[512+(r+8)*4+3];
            mean0[ma] = s0 * (1.0f / 256.0f);
            inv0[ma]  = rsqrtf(q0 * (1.0f / 256.0f) - mean0[ma] * mean0[ma] + 1e-5f);
            mean1[ma] = s1 * (1.0f / 256.0f);
            inv1[ma]  = rsqrtf(q1 * (1.0f / 256.0f) - mean1[ma] * mean1[ma] + 1e-5f);
        }
        __syncthreads();
    };

    __syncthreads();
    if (MODE == 7 && g1 == nullptr) {
        #pragma unroll
        for (int ma = 0; ma < 4; ma++) {
            const long r0 = bm + wm * 64 + ma * 16 + g;
            #pragma unroll
            for (int nb = 0; nb < 8; nb++) {
                st2(xo + r0 * D_ + colb + nb * 8,       acc[ma][nb][0], acc[ma][nb][1]);
                st2(xo + (r0 + 8) * D_ + colb + nb * 8, acc[ma][nb][2], acc[ma][nb][3]);
            }
        }
        return;
    }

    reduce_rows();

    float2 g1v[8], b1vv[8];
    #pragma unroll
    for (int nb = 0; nb < 8; nb++) {
        g1v[nb]  = *(const float2*)(g1 + colb + nb * 8);
        b1vv[nb] = *(const float2*)(b1v + colb + nb * 8);
    }

    if (MODE == 7) {
        #pragma unroll
        for (int ma = 0; ma < 4; ma++) {
            const long r0 = bm + wm * 64 + ma * 16 + g;
            #pragma unroll
            for (int nb = 0; nb < 8; nb++) {
                const int cc = colb + nb * 8;
                float x0 = acc[ma][nb][0], x1 = acc[ma][nb][1];
                float x2 = acc[ma][nb][2], x3 = acc[ma][nb][3];
                st2(xo + r0 * D_ + cc, x0, x1);
                st2(xo + (r0 + 8) * D_ + cc, x2, x3);
                float h0 = (x0 - mean0[ma]) * inv0[ma] * g1v[nb].x + b1vv[nb].x;
                float h1 = (x1 - mean0[ma]) * inv0[ma] * g1v[nb].y + b1vv[nb].y;
                float h2 = (x2 - mean1[ma]) * inv1[ma] * g1v[nb].x + b1vv[nb].x;
                float h3 = (x3 - mean1[ma]) * inv1[ma] * g1v[nb].y + b1vv[nb].y;
                st2(out32 + r0 * D_ + cc, h0, h1);
                st2(out32 + (r0 + 8) * D_ + cc, h2, h3);
                st2(out16 + r0 * D_ + cc, h0, h1);
                st2(out16 + (r0 + 8) * D_ + cc, h2, h3);
            }
        }
        return;
    }

    // MODE 6: x = h32 + LN(t); second LN for C16
    #pragma unroll
    for (int ma = 0; ma < 4; ma++) {
        const long r0 = bm + wm * 64 + ma * 16 + g;
        #pragma unroll
        for (int nb = 0; nb < 8; nb++) {
            const int cc = colb + nb * 8;
            float2 ha = *(const float2*)(res32 + r0 * D_ + cc);
            float2 hb = *(const float2*)(res32 + (r0 + 8) * D_ + cc);
            acc[ma][nb][0] = ha.x + (acc[ma][nb][0] - mean0[ma]) * inv0[ma] * g1v[nb].x + b1vv[nb].x;
            acc[ma][nb][1] = ha.y + (acc[ma][nb][1] - mean0[ma]) * inv0[ma] * g1v[nb].y + b1vv[nb].y;
            acc[ma][nb][2] = hb.x + (acc[ma][nb][2] - mean1[ma]) * inv1[ma] * g1v[nb].x + b1vv[nb].x;
            acc[ma][nb][3] = hb.y + (acc[ma][nb][3] - mean1[ma]) * inv1[ma] * g1v[nb].y + b1vv[nb].y;
        }
    }
    reduce_rows();

    #pragma unroll
    for (int nb = 0; nb < 8; nb++) {
        g1v[nb]  = *(const float2*)(g2 + colb + nb * 8);
        b1vv[nb] = *(const float2*)(b2v + colb + nb * 8);
    }
    #pragma unroll
    for (int ma = 0; ma < 4; ma++) {
        const long r0 = bm + wm * 64 + ma * 16 + g;
        #pragma unroll
        for (int nb = 0; nb < 8; nb++) {
            const int cc = colb + nb * 8;
            float x0 = acc[ma][nb][0], x1 = acc[ma][nb][1];
            float x2 = acc[ma][nb][2], x3 = acc[ma][nb][3];
            st2(xo + r0 * D_ + cc, x0, x1);
            st2(xo + (r0 + 8) * D_ + cc, x2, x3);
            float c0 = (x0 - mean0[ma]) * inv0[ma] * g1v[nb].x + b1vv[nb].x;
            float c1 = (x1 - mean0[ma]) * inv0[ma] * g1v[nb].y + b1vv[nb].y;
            float c2 = (x2 - mean1[ma]) * inv1[ma] * g1v[nb].x + b1vv[nb].x;
            float c3 = (x3 - mean1[ma]) * inv1[ma] * g1v[nb].y + b1vv[nb].y;
            st2(out16 + r0 * D_ + cc, c0, c1);
            st2(out16 + (r0 + 8) * D_ + cc, c2, c3);
        }
    }
}
#define WSMEM 98304

// ---------------------------------------------------------------------------
// Launcher
// ---------------------------------------------------------------------------
extern "C" void kernel_launch(void* const* d_in, const int* in_sizes, int n_in,
                              void* d_out, int out_size)
{
    const float* x    = (const float*)d_in[0];
    const int*   mask = (const int*)  d_in[1];
    const float* btab = (const float*)d_in[2];
    const float* ln_g = (const float*)d_in[3];
    const float* ln_b = (const float*)d_in[4];
    const float* wq   = (const float*)d_in[5];
    const float* bq   = (const float*)d_in[6];
    const float* wk   = (const float*)d_in[7];
    const float* bk   = (const float*)d_in[8];
    const float* wv   = (const float*)d_in[9];
    const float* bv   = (const float*)d_in[10];
    const float* wo   = (const float*)d_in[11];
    const float* bo   = (const float*)d_in[12];
    const float* cmg  = (const float*)d_in[13];
    const float* cmb  = (const float*)d_in[14];
    const float* w1   = (const float*)d_in[15];
    const float* b1   = (const float*)d_in[16];
    const float* w2   = (const float*)d_in[17];
    const float* b2   = (const float*)d_in[18];
    float* xo = (float*)d_out;

    __half *H16, *Q16, *K16, *V16, *O16, *C16, *F16, *WT, *WQKV;
    float *H32;
    cudaGetSymbolAddress((void**)&H16,  g_H16);
    cudaGetSymbolAddress((void**)&Q16,  g_Q16);
    cudaGetSymbolAddress((void**)&K16,  g_K16);
    cudaGetSymbolAddress((void**)&V16,  g_V16);
    cudaGetSymbolAddress((void**)&O16,  g_O16);
    cudaGetSymbolAddress((void**)&C16,  g_C16);
    cudaGetSymbolAddress((void**)&F16,  g_F16);
    cudaGetSymbolAddress((void**)&WT,   g_WT16);
    cudaGetSymbolAddress((void**)&WQKV, g_WQKV);
    cudaGetSymbolAddress((void**)&H32,  g_H32);

    cudaFuncSetAttribute(gemm_k<5, __half>, cudaFuncAttributeMaxDynamicSharedMemorySize, GSMEM);
    cudaFuncSetAttribute(gemm_k<2, __half>, cudaFuncAttributeMaxDynamicSharedMemorySize, GSMEM);
    cudaFuncSetAttribute(gemmw_k<6>, cudaFuncAttributeMaxDynamicSharedMemorySize, WSMEM);
    cudaFuncSetAttribute(gemmw_k<7>, cudaFuncAttributeMaxDynamicSharedMemorySize, WSMEM);
    cudaFuncSetAttribute(flash_k, cudaFuncAttributeMaxDynamicSharedMemorySize, FSMEM);

    // weight transposes: 3 launches (so the first flash is the 6th kernel launch
    // -> ncu -s 5 -c 1 profiles flash next capture)
    const dim3 trB(32, 8);
    trW3_k<<<dim3(8, 8, 9), trB>>>(wq, wk, wv, WQKV, WSZ, 3L * WSZ, 3, D_, D_);
    trW3_k<<<dim3(8, 8, 6), trB>>>(wo, w1, w1, WT, 3L * WSZ, WSZ, 3, D_, D_);
    trW3_k<<<dim3(8, 8, 3), trB>>>(w2, w2, w2, WT + 2L * 3 * WSZ, 0, WSZ, 3, D_, D_);

    const dim3 gQKV(6, ROWS / 128, 1);
    const dim3 gProj(D_ / 128, ROWS / 128, 1);
    const dim3 gWide(1, ROWS / 128, 1);
    const dim3 gFlash(S_ / 64, 1, B_);
    const int  rowBlocks = ROWS / 8;

    // layer-0 input LN  (launch #4)
    ln_k<<<rowBlocks, 256>>>(x, ln_g, ln_b, H16, H32, ROWS);

    for (int j = 0; j < 3; j++) {
        const float* gj = ln_g + j * D_;
        const float* bj = ln_b + j * D_;
        const __half* wqkvT = WQKV + (long)j * 3 * WSZ;
        const __half* woT   = WT + (0L * 3 + j) * WSZ;
        const __half* w1T   = WT + (1L * 3 + j) * WSZ;
        const __half* w2T   = WT + (2L * 3 + j) * WSZ;

        // q,k,v = h @ {wq,wk,wv} + bias (fused, routed)   (launch #5 on j=0)
        gemm_k<5, __half><<<gQKV, 128, GSMEM>>>(H16, wqkvT, bq + j * D_, Q16,
                                                ROWS, 768, D_,
                                                K16, V16, bk + j * D_, bv + j * D_);

        // o = attention(q, k, v)                          (launch #6 on j=0)
        flash_k<<<gFlash, 256, FSMEM>>>(Q16, K16, V16, mask, btab, O16);

        // x = h + LN(o@wo+bo); c = LN_cm(x)
        gemmw_k<6><<<gWide, 256, WSMEM>>>(O16, woT, bo + j * D_, H32,
                                          xo, C16, nullptr,
                                          gj, bj, cmg + j * D_, cmb + j * D_);

        // f = gelu(c @ w1 + b1)
        gemm_k<2, __half><<<gProj, 128, GSMEM>>>(C16, w1T, b1 + j * D_, F16,
                                                 ROWS, D_, D_,
                                                 (__half*)nullptr, (__half*)nullptr, nullptr, nullptr);

        // x = x + f@w2 + b2 ; h_next = LN(x) (layers 0,1)
        const bool last = (j == 2);
        gemmw_k<7><<<gWide, 256, WSMEM>>>(F16, w2T, b2 + j * D_, xo,
                                          xo, last ? nullptr : H16,
                                          last ? nullptr : H32,
                                          last ? nullptr : ln_g + (j + 1) * D_,
                                          last ? nullptr : ln_b + (j + 1) * D_,
                                          nullptr, nullptr);
    }
}